// round 5
// baseline (speedup 1.0000x reference)
#include <cuda_runtime.h>

#define BB 16
#define NN 256
#define FF 64
#define DD 128
#define HH 4
#define DHH 32
#define DFF_ 512
#define LL 2
#define ROWS (BB*NN)     // 4096
#define PP (NN*(NN-1))   // 65280
#define EPSF 1e-5f

// ---------------- scratch ----------------
__device__ float g_x[ROWS*DD];
__device__ float g_qkv[ROWS*3*DD];
__device__ float g_attn[ROWS*DD];
__device__ float g_ffn[ROWS*DFF_];
__device__ float g_A[ROWS*DD];
__device__ float g_Bm[ROWS*DD];

typedef unsigned long long u64;

__device__ __forceinline__ u64 pack2(float x, float y) {
  u64 r; asm("mov.b64 %0, {%1, %2};" : "=l"(r) : "f"(x), "f"(y)); return r;
}
__device__ __forceinline__ float2 unpack2(u64 v) {
  float2 r; asm("mov.b64 {%0, %1}, %2;" : "=f"(r.x), "=f"(r.y) : "l"(v)); return r;
}
__device__ __forceinline__ void ffma2(u64 &d, u64 a, u64 b) {
  asm("fma.rn.f32x2 %0, %1, %2, %0;" : "+l"(d) : "l"(a), "l"(b));
}
__device__ __forceinline__ u64 ffma2_o(u64 a, u64 b, u64 c) {
  u64 o; asm("fma.rn.f32x2 %0, %1, %2, %3;" : "=l"(o) : "l"(a), "l"(b), "l"(c)); return o;
}
__device__ __forceinline__ u64 add2(u64 a, u64 b) {
  u64 o; asm("add.rn.f32x2 %0, %1, %2;" : "=l"(o) : "l"(a), "l"(b)); return o;
}
__device__ __forceinline__ u64 relu2(u64 v) {
  float2 f = unpack2(v);
  return pack2(fmaxf(f.x, 0.f), fmaxf(f.y, 0.f));
}

// ================ unified GEMM: BM=32, BN=128 slice, BK=16, 128 threads, 4x8 tile ================
// EPI: 0 = +bias ; 1 = +bias,relu ; 2 = +bias,+res,LN ; 3 = +bias,relu,LN ;
//      5 = pairpre dual (blockIdx.z selects W half / output; bias only half 0)
template <int EPI>
__global__ void __launch_bounds__(128) k_gemm(
    const float* __restrict__ X, int KK,
    const float* __restrict__ W, int NOUT,
    const float* __restrict__ bias,
    float* __restrict__ Y, float* __restrict__ Y2,
    const float* __restrict__ res,
    const float* __restrict__ g, const float* __restrict__ beta) {
  __shared__ float As[2][16][32];
  __shared__ float Bs[2][16][128];
  const int t  = threadIdx.x;
  const int tx = t & 15, ty = t >> 4;
  const int bm0 = blockIdx.x * 32;
  const int bn0 = blockIdx.y * 128;
  const int r0 = ty * 4, c0 = tx * 8;
  const int am = t >> 2,  akq = (t & 3) * 4;
  const int bkr = t >> 3, bcq = (t & 7) * 16;

  if (EPI == 5) {
    if (blockIdx.z) { W += (size_t)KK * NOUT; Y = Y2; bias = nullptr; }
  }

  u64 acc[4][4];
  {
    u64 i0 = 0, i1 = 0, i2 = 0, i3 = 0;
    if (EPI != 5 || bias) {
      float4 bv0 = *(const float4*)&bias[bn0 + c0];
      float4 bv1 = *(const float4*)&bias[bn0 + c0 + 4];
      i0 = pack2(bv0.x, bv0.y); i1 = pack2(bv0.z, bv0.w);
      i2 = pack2(bv1.x, bv1.y); i3 = pack2(bv1.z, bv1.w);
    }
    #pragma unroll
    for (int i = 0; i < 4; i++) { acc[i][0]=i0; acc[i][1]=i1; acc[i][2]=i2; acc[i][3]=i3; }
  }

  const float* Xp = X + (size_t)(bm0 + am) * KK + akq;
  const float* Wp = W + (size_t)bkr * NOUT + bn0 + bcq;
  const int NT = KK >> 4;

  float4 a0 = *(const float4*)Xp;
  float4 b0 = *(const float4*)Wp;
  float4 b1 = *(const float4*)(Wp + 4);
  float4 b2 = *(const float4*)(Wp + 8);
  float4 b3 = *(const float4*)(Wp + 12);
  {
    As[0][akq + 0][am] = a0.x; As[0][akq + 1][am] = a0.y;
    As[0][akq + 2][am] = a0.z; As[0][akq + 3][am] = a0.w;
    *(float4*)&Bs[0][bkr][bcq]      = b0;
    *(float4*)&Bs[0][bkr][bcq + 4]  = b1;
    *(float4*)&Bs[0][bkr][bcq + 8]  = b2;
    *(float4*)&Bs[0][bkr][bcq + 12] = b3;
  }
  __syncthreads();

  for (int it = 0; it < NT; it++) {
    const int buf = it & 1;
    if (it + 1 < NT) {
      a0 = *(const float4*)(Xp + (it + 1) * 16);
      const float* wp = Wp + (size_t)(it + 1) * 16 * NOUT;
      b0 = *(const float4*)wp;        b1 = *(const float4*)(wp + 4);
      b2 = *(const float4*)(wp + 8);  b3 = *(const float4*)(wp + 12);
    }
    #pragma unroll
    for (int k = 0; k < 16; k++) {
      float4 av = *(const float4*)&As[buf][k][r0];
      ulonglong2 bv0 = *(const ulonglong2*)&Bs[buf][k][c0];
      ulonglong2 bv1 = *(const ulonglong2*)&Bs[buf][k][c0 + 4];
      u64 pa0 = pack2(av.x, av.x);
      u64 pa1 = pack2(av.y, av.y);
      u64 pa2 = pack2(av.z, av.z);
      u64 pa3 = pack2(av.w, av.w);
      ffma2(acc[0][0], pa0, bv0.x); ffma2(acc[0][1], pa0, bv0.y);
      ffma2(acc[0][2], pa0, bv1.x); ffma2(acc[0][3], pa0, bv1.y);
      ffma2(acc[1][0], pa1, bv0.x); ffma2(acc[1][1], pa1, bv0.y);
      ffma2(acc[1][2], pa1, bv1.x); ffma2(acc[1][3], pa1, bv1.y);
      ffma2(acc[2][0], pa2, bv0.x); ffma2(acc[2][1], pa2, bv0.y);
      ffma2(acc[2][2], pa2, bv1.x); ffma2(acc[2][3], pa2, bv1.y);
      ffma2(acc[3][0], pa3, bv0.x); ffma2(acc[3][1], pa3, bv0.y);
      ffma2(acc[3][2], pa3, bv1.x); ffma2(acc[3][3], pa3, bv1.y);
    }
    if (it + 1 < NT) {
      const int nb = buf ^ 1;
      As[nb][akq + 0][am] = a0.x; As[nb][akq + 1][am] = a0.y;
      As[nb][akq + 2][am] = a0.z; As[nb][akq + 3][am] = a0.w;
      *(float4*)&Bs[nb][bkr][bcq]      = b0;
      *(float4*)&Bs[nb][bkr][bcq + 4]  = b1;
      *(float4*)&Bs[nb][bkr][bcq + 8]  = b2;
      *(float4*)&Bs[nb][bkr][bcq + 12] = b3;
    }
    __syncthreads();
  }

  #pragma unroll
  for (int i = 0; i < 4; i++) {
    const int row = bm0 + r0 + i;
    float f[8];
    #pragma unroll
    for (int j = 0; j < 4; j++) {
      float2 u = unpack2(acc[i][j]);
      f[2 * j] = u.x; f[2 * j + 1] = u.y;
    }
    if (EPI == 1 || EPI == 3) {
      #pragma unroll
      for (int j = 0; j < 8; j++) f[j] = fmaxf(f[j], 0.f);
    }
    if (EPI == 2) {
      float4 r0v = *(const float4*)&res[(size_t)row * DD + c0];
      float4 r1v = *(const float4*)&res[(size_t)row * DD + c0 + 4];
      f[0] += r0v.x; f[1] += r0v.y; f[2] += r0v.z; f[3] += r0v.w;
      f[4] += r1v.x; f[5] += r1v.y; f[6] += r1v.z; f[7] += r1v.w;
    }
    if (EPI == 2 || EPI == 3) {
      float s = 0.f, s2 = 0.f;
      #pragma unroll
      for (int j = 0; j < 8; j++) { s += f[j]; s2 += f[j] * f[j]; }
      #pragma unroll
      for (int o = 8; o; o >>= 1) {
        s  += __shfl_xor_sync(0xffffffffu, s,  o);
        s2 += __shfl_xor_sync(0xffffffffu, s2, o);
      }
      float mu = s * (1.f / 128.f);
      float var = s2 * (1.f / 128.f) - mu * mu;
      float rstd = rsqrtf(var + EPSF);
      float4 g0 = *(const float4*)&g[c0];
      float4 g1 = *(const float4*)&g[c0 + 4];
      float4 e0 = *(const float4*)&beta[c0];
      float4 e1 = *(const float4*)&beta[c0 + 4];
      f[0] = (f[0] - mu) * rstd * g0.x + e0.x;
      f[1] = (f[1] - mu) * rstd * g0.y + e0.y;
      f[2] = (f[2] - mu) * rstd * g0.z + e0.z;
      f[3] = (f[3] - mu) * rstd * g0.w + e0.w;
      f[4] = (f[4] - mu) * rstd * g1.x + e1.x;
      f[5] = (f[5] - mu) * rstd * g1.y + e1.y;
      f[6] = (f[6] - mu) * rstd * g1.z + e1.z;
      f[7] = (f[7] - mu) * rstd * g1.w + e1.w;
    }
    float* yp = &Y[(size_t)row * NOUT + bn0 + c0];
    *(float4*)yp       = make_float4(f[0], f[1], f[2], f[3]);
    *(float4*)(yp + 4) = make_float4(f[4], f[5], f[6], f[7]);
  }
}

// ================ attention: single-pass, block = (qtile, h, b), 128 threads ================
__global__ void __launch_bounds__(128) k_attn(const float* __restrict__ qkv,
                                              float* __restrict__ out) {
  extern __shared__ float sm[];
  float* Ks = sm;            // [256][32]
  float* Vs = sm + NN * DHH; // [256][32]
  const int qt = blockIdx.x, h = blockIdx.y, b = blockIdx.z;
  const int q = qt * 128 + threadIdx.x;
  const float* base = qkv + (size_t)b * NN * (3 * DD);
  const int hoff = h * DHH;

  for (int idx = threadIdx.x; idx < NN * DHH / 4; idx += 128) {
    int r = idx >> 3, d4 = (idx & 7) << 2;
    *(float4*)&Ks[r * DHH + d4] = *(const float4*)&base[(size_t)r * (3 * DD) + DD     + hoff + d4];
    *(float4*)&Vs[r * DHH + d4] = *(const float4*)&base[(size_t)r * (3 * DD) + 2 * DD + hoff + d4];
  }
  u64 qp[16];
  {
    const ulonglong2* qptr = (const ulonglong2*)(base + (size_t)q * (3 * DD) + hoff);
    #pragma unroll
    for (int i = 0; i < 8; i++) { ulonglong2 u = qptr[i]; qp[2*i] = u.x; qp[2*i+1] = u.y; }
  }
  __syncthreads();

  float m = -1e30f, l = 0.f;
  u64 op[16];
  #pragma unroll
  for (int i = 0; i < 16; i++) op[i] = 0ull;
  const float scale = 0.17677669529663687f;  // 1/sqrt(32)

  for (int k = 0; k < NN; k++) {
    const ulonglong2* kr = (const ulonglong2*)&Ks[k * DHH];
    u64 sp0 = 0, sp1 = 0, sp2 = 0, sp3 = 0;
    #pragma unroll
    for (int i = 0; i < 4; i++) {
      ulonglong2 ka = kr[2*i], kb = kr[2*i+1];
      ffma2(sp0, qp[4*i],     ka.x);
      ffma2(sp1, qp[4*i + 1], ka.y);
      ffma2(sp2, qp[4*i + 2], kb.x);
      ffma2(sp3, qp[4*i + 3], kb.y);
    }
    float2 u0 = unpack2(sp0), u1 = unpack2(sp1), u2 = unpack2(sp2), u3 = unpack2(sp3);
    float s = ((u0.x + u0.y) + (u1.x + u1.y)) + ((u2.x + u2.y) + (u3.x + u3.y));
    s *= scale;
    const ulonglong2* vr = (const ulonglong2*)&Vs[k * DHH];
    if (s > m) {
      float c = __expf(m - s);
      m = s;
      l = l * c + 1.f;
      u64 cp = pack2(c, c);
      #pragma unroll
      for (int i = 0; i < 8; i++) {
        ulonglong2 vv = vr[i];
        op[2*i]     = ffma2_o(op[2*i],     cp, vv.x);
        op[2*i + 1] = ffma2_o(op[2*i + 1], cp, vv.y);
      }
    } else {
      float p = __expf(s - m);
      l += p;
      u64 pp = pack2(p, p);
      #pragma unroll
      for (int i = 0; i < 8; i++) {
        ulonglong2 vv = vr[i];
        ffma2(op[2*i],     pp, vv.x);
        ffma2(op[2*i + 1], pp, vv.y);
      }
    }
  }
  const float inv = 1.f / l;
  float* optr = out + (size_t)(b * NN + q) * DD + hoff;
  #pragma unroll
  for (int i = 0; i < 8; i++) {
    float2 a = unpack2(op[2*i]), c = unpack2(op[2*i + 1]);
    *(float4*)&optr[4*i] = make_float4(a.x * inv, a.y * inv, c.x * inv, c.y * inv);
  }
}

// ================ pair kernel: 64i x 64j per block, 4x4 pairs per thread ================
#define SP 132  // padded row stride (floats)
__global__ void __launch_bounds__(256) k_pair(const float* __restrict__ w2,
                                              const float* __restrict__ b2,
                                              float* __restrict__ out) {
  extern __shared__ float sm[];
  float* smA = sm;                   // 64*SP
  float* smB = sm + 64 * SP;         // 64*SP
  float* smw = sm + 128 * SP;        // 128
  const int b  = blockIdx.z;
  const int i0 = blockIdx.x * 64;
  const int j0 = blockIdx.y * 64;
  const int t  = threadIdx.x;  // 256
  const int jx = t & 15, iy = t >> 4;

  {
    const float* Ab = g_A  + ((size_t)(b * NN + i0)) * DD;
    const float* Bb = g_Bm + ((size_t)(b * NN + j0)) * DD;
    for (int idx = t; idx < 64 * 32; idx += 256) {
      int r = idx >> 5, dq = (idx & 31) << 2;
      *(float4*)&smA[r * SP + dq] = *(const float4*)&Ab[(size_t)r * DD + dq];
      *(float4*)&smB[r * SP + dq] = *(const float4*)&Bb[(size_t)r * DD + dq];
    }
    if (t < 32) *(float4*)&smw[t * 4] = *(const float4*)&w2[t * 4];
  }
  __syncthreads();

  const int ibl = iy * 4;
  u64 acc[4][4];
  #pragma unroll
  for (int ii = 0; ii < 4; ii++)
    #pragma unroll
    for (int jj = 0; jj < 4; jj++) acc[ii][jj] = 0ull;

  for (int d = 0; d < DD; d += 4) {
    ulonglong2 wv = *(const ulonglong2*)&smw[d];
    ulonglong2 av[4], bv[4];
    #pragma unroll
    for (int ii = 0; ii < 4; ii++) av[ii] = *(const ulonglong2*)&smA[(ibl + ii) * SP + d];
    #pragma unroll
    for (int jj = 0; jj < 4; jj++) bv[jj] = *(const ulonglong2*)&smB[(jx + 16 * jj) * SP + d];
    #pragma unroll
    for (int ii = 0; ii < 4; ii++) {
      #pragma unroll
      for (int jj = 0; jj < 4; jj++) {
        u64 s0 = relu2(add2(av[ii].x, bv[jj].x));
        ffma2(acc[ii][jj], s0, wv.x);
        u64 s1 = relu2(add2(av[ii].y, bv[jj].y));
        ffma2(acc[ii][jj], s1, wv.y);
      }
    }
  }

  const float b2v = b2[0];
  float* outb = out + (size_t)b * PP;
  #pragma unroll
  for (int ii = 0; ii < 4; ii++) {
    const int i = i0 + ibl + ii;
    #pragma unroll
    for (int jj = 0; jj < 4; jj++) {
      const int j = j0 + jx + 16 * jj;
      if (j != i) {
        float2 u = unpack2(acc[ii][jj]);
        outb[i * (NN - 1) + j - (j > i ? 1 : 0)] = u.x + u.y + b2v;
      }
    }
  }
}

// ================ host ================
extern "C" void kernel_launch(void* const* d_in, const int* in_sizes, int n_in,
                              void* d_out, int out_size) {
  const float* agents   = (const float*)d_in[0];
  const float* enc_w    = (const float*)d_in[1];
  const float* enc_b    = (const float*)d_in[2];
  const float* enc_g    = (const float*)d_in[3];
  const float* enc_beta = (const float*)d_in[4];
  const float* qkv_w    = (const float*)d_in[5];
  const float* qkv_b    = (const float*)d_in[6];
  const float* attn_ow  = (const float*)d_in[7];
  const float* attn_ob  = (const float*)d_in[8];
  const float* ln1_g    = (const float*)d_in[9];
  const float* ln1_b    = (const float*)d_in[10];
  const float* ffn_w1   = (const float*)d_in[11];
  const float* ffn_b1   = (const float*)d_in[12];
  const float* ffn_w2   = (const float*)d_in[13];
  const float* ffn_b2   = (const float*)d_in[14];
  const float* ln2_g    = (const float*)d_in[15];
  const float* ln2_b    = (const float*)d_in[16];
  const float* rel_w1   = (const float*)d_in[17];
  const float* rel_b1   = (const float*)d_in[18];
  const float* rel_w2   = (const float*)d_in[19];
  const float* rel_b2   = (const float*)d_in[20];
  float* out = (float*)d_out;

  float *px, *pqkv, *pattn, *pffn, *pA, *pBm;
  cudaGetSymbolAddress((void**)&px,    g_x);
  cudaGetSymbolAddress((void**)&pqkv,  g_qkv);
  cudaGetSymbolAddress((void**)&pattn, g_attn);
  cudaGetSymbolAddress((void**)&pffn,  g_ffn);
  cudaGetSymbolAddress((void**)&pA,    g_A);
  cudaGetSymbolAddress((void**)&pBm,   g_Bm);

  const int attn_smem = NN * DHH * 2 * sizeof(float);      // 64KB
  const int pair_smem = (128 * SP + 128) * sizeof(float);  // ~66KB
  cudaFuncSetAttribute(k_attn, cudaFuncAttributeMaxDynamicSharedMemorySize, attn_smem);
  cudaFuncSetAttribute(k_pair, cudaFuncAttributeMaxDynamicSharedMemorySize, pair_smem);

  // encoder: relu(agents @ enc_w + b) -> LN   (K=64, N=128)
  k_gemm<3><<<ROWS / 32, 128>>>(agents, FF, enc_w, DD, enc_b, px, nullptr,
                                nullptr, enc_g, enc_beta);

  for (int l = 0; l < LL; l++) {
    k_gemm<0><<<dim3(ROWS / 32, 3), 128>>>(px, DD, qkv_w + (size_t)l * DD * 3 * DD,
                                           3 * DD, qkv_b + (size_t)l * 3 * DD, pqkv,
                                           nullptr, nullptr, nullptr, nullptr);
    k_attn<<<dim3(2, HH, BB), 128, attn_smem>>>(pqkv, pattn);
    k_gemm<2><<<ROWS / 32, 128>>>(pattn, DD, attn_ow + (size_t)l * DD * DD, DD,
                                  attn_ob + (size_t)l * DD, px, nullptr,
                                  px, ln1_g + (size_t)l * DD, ln1_b + (size_t)l * DD);
    k_gemm<1><<<dim3(ROWS / 32, 4), 128>>>(px, DD, ffn_w1 + (size_t)l * DD * DFF_,
                                           DFF_, ffn_b1 + (size_t)l * DFF_, pffn,
                                           nullptr, nullptr, nullptr, nullptr);
    k_gemm<2><<<ROWS / 32, 128>>>(pffn, DFF_, ffn_w2 + (size_t)l * DFF_ * DD, DD,
                                  ffn_b2 + (size_t)l * DD, px, nullptr,
                                  px, ln2_g + (size_t)l * DD, ln2_b + (size_t)l * DD);
  }

  // pair precompute: A = x@W1[:D]+b1 ; Bm = x@W1[D:]
  k_gemm<5><<<dim3(ROWS / 32, 1, 2), 128>>>(px, DD, rel_w1, DD, rel_b1, pA, pBm,
                                            nullptr, nullptr, nullptr);

  k_pair<<<dim3(NN / 64, NN / 64, BB), 256, pair_smem>>>(rel_w2, rel_b2, out);
}

// round 6
// speedup vs baseline: 1.2091x; 1.2091x over previous
#include <cuda_runtime.h>

#define BB 16
#define NN 256
#define FF 64
#define DD 128
#define HH 4
#define DHH 32
#define DFF_ 512
#define LL 2
#define ROWS (BB*NN)     // 4096
#define PP (NN*(NN-1))   // 65280
#define EPSF 1e-5f
#define SPLITS 2
#define BHQ (BB*HH*NN)   // 16384

// ---------------- scratch ----------------
__device__ float g_x[ROWS*DD];
__device__ float g_qkv[ROWS*3*DD];    // qkv; later reused for GEMM split-K partials (2*524288 floats)
__device__ float g_ffn[ROWS*DFF_];    // ffn1 acts; also attention po scratch (SPLITS*BHQ*32 = 1048576)
__device__ float g_A[ROWS*DD];        // pairpre A; also attention ml scratch (SPLITS*BHQ*2 = 65536)
__device__ float g_Bm[ROWS*DD];

typedef unsigned long long u64;

__device__ __forceinline__ u64 pack2(float x, float y) {
  u64 r; asm("mov.b64 %0, {%1, %2};" : "=l"(r) : "f"(x), "f"(y)); return r;
}
__device__ __forceinline__ float2 unpack2(u64 v) {
  float2 r; asm("mov.b64 {%0, %1}, %2;" : "=f"(r.x), "=f"(r.y) : "l"(v)); return r;
}
__device__ __forceinline__ void ffma2(u64 &d, u64 a, u64 b) {
  asm("fma.rn.f32x2 %0, %1, %2, %0;" : "+l"(d) : "l"(a), "l"(b));
}
__device__ __forceinline__ u64 ffma2_o(u64 a, u64 b, u64 c) {
  u64 o; asm("fma.rn.f32x2 %0, %1, %2, %3;" : "=l"(o) : "l"(a), "l"(b), "l"(c)); return o;
}
__device__ __forceinline__ u64 add2(u64 a, u64 b) {
  u64 o; asm("add.rn.f32x2 %0, %1, %2;" : "=l"(o) : "l"(a), "l"(b)); return o;
}
__device__ __forceinline__ u64 relu2(u64 v) {
  float2 f = unpack2(v);
  return pack2(fmaxf(f.x, 0.f), fmaxf(f.y, 0.f));
}

// ================ GEMM A: BM=64, BN=128, BK=16, 128 threads, 8x8 thread tile ================
// EPI: 0 = +bias ; 1 = +bias,relu ; 5 = pairpre dual (blockIdx.z selects W half / output)
template <int EPI>
__global__ void __launch_bounds__(128) k_gemmA(
    const float* __restrict__ X, int KK,
    const float* __restrict__ W, int NOUT,
    const float* __restrict__ bias,
    float* __restrict__ Y, float* __restrict__ Y2) {
  __shared__ float As[2][16][64];
  __shared__ float Bs[2][16][128];
  const int t  = threadIdx.x;
  const int tx = t & 15, ty = t >> 4;
  const int bm0 = blockIdx.x * 64, bn0 = blockIdx.y * 128;
  const int r0 = ty * 8, c0 = tx * 8;
  const int am = t >> 1,  akq = (t & 1) * 8;
  const int bkr = t >> 3, bcq = (t & 7) * 16;

  if (EPI == 5) {
    if (blockIdx.z) { W += (size_t)KK * NOUT; Y = Y2; bias = nullptr; }
  }

  u64 acc[8][4];
  {
    u64 i0 = 0, i1 = 0, i2 = 0, i3 = 0;
    if (EPI != 5 || bias) {
      if (bias) {
        float4 bv0 = *(const float4*)&bias[bn0 + c0];
        float4 bv1 = *(const float4*)&bias[bn0 + c0 + 4];
        i0 = pack2(bv0.x, bv0.y); i1 = pack2(bv0.z, bv0.w);
        i2 = pack2(bv1.x, bv1.y); i3 = pack2(bv1.z, bv1.w);
      }
    }
    #pragma unroll
    for (int i = 0; i < 8; i++) { acc[i][0]=i0; acc[i][1]=i1; acc[i][2]=i2; acc[i][3]=i3; }
  }

  const float* Xp = X + (size_t)(bm0 + am) * KK + akq;
  const float* Wp = W + (size_t)bkr * NOUT + bn0 + bcq;
  const int NT = KK >> 4;

  float4 a0 = *(const float4*)Xp;
  float4 a1 = *(const float4*)(Xp + 4);
  float4 b0 = *(const float4*)Wp;
  float4 b1 = *(const float4*)(Wp + 4);
  float4 b2 = *(const float4*)(Wp + 8);
  float4 b3 = *(const float4*)(Wp + 12);
  {
    As[0][akq + 0][am] = a0.x; As[0][akq + 1][am] = a0.y;
    As[0][akq + 2][am] = a0.z; As[0][akq + 3][am] = a0.w;
    As[0][akq + 4][am] = a1.x; As[0][akq + 5][am] = a1.y;
    As[0][akq + 6][am] = a1.z; As[0][akq + 7][am] = a1.w;
    *(float4*)&Bs[0][bkr][bcq]      = b0;
    *(float4*)&Bs[0][bkr][bcq + 4]  = b1;
    *(float4*)&Bs[0][bkr][bcq + 8]  = b2;
    *(float4*)&Bs[0][bkr][bcq + 12] = b3;
  }
  __syncthreads();

  for (int it = 0; it < NT; it++) {
    const int buf = it & 1;
    if (it + 1 < NT) {
      const float* xp = Xp + (it + 1) * 16;
      a0 = *(const float4*)xp; a1 = *(const float4*)(xp + 4);
      const float* wp = Wp + (size_t)(it + 1) * 16 * NOUT;
      b0 = *(const float4*)wp;        b1 = *(const float4*)(wp + 4);
      b2 = *(const float4*)(wp + 8);  b3 = *(const float4*)(wp + 12);
    }
    #pragma unroll
    for (int k = 0; k < 16; k++) {
      float4 av0 = *(const float4*)&As[buf][k][r0];
      float4 av1 = *(const float4*)&As[buf][k][r0 + 4];
      ulonglong2 bv0 = *(const ulonglong2*)&Bs[buf][k][c0];
      ulonglong2 bv1 = *(const ulonglong2*)&Bs[buf][k][c0 + 4];
      u64 pa[8];
      pa[0] = pack2(av0.x, av0.x); pa[1] = pack2(av0.y, av0.y);
      pa[2] = pack2(av0.z, av0.z); pa[3] = pack2(av0.w, av0.w);
      pa[4] = pack2(av1.x, av1.x); pa[5] = pack2(av1.y, av1.y);
      pa[6] = pack2(av1.z, av1.z); pa[7] = pack2(av1.w, av1.w);
      #pragma unroll
      for (int i = 0; i < 8; i++) {
        ffma2(acc[i][0], pa[i], bv0.x);
        ffma2(acc[i][1], pa[i], bv0.y);
        ffma2(acc[i][2], pa[i], bv1.x);
        ffma2(acc[i][3], pa[i], bv1.y);
      }
    }
    if (it + 1 < NT) {
      const int nb = buf ^ 1;
      As[nb][akq + 0][am] = a0.x; As[nb][akq + 1][am] = a0.y;
      As[nb][akq + 2][am] = a0.z; As[nb][akq + 3][am] = a0.w;
      As[nb][akq + 4][am] = a1.x; As[nb][akq + 5][am] = a1.y;
      As[nb][akq + 6][am] = a1.z; As[nb][akq + 7][am] = a1.w;
      *(float4*)&Bs[nb][bkr][bcq]      = b0;
      *(float4*)&Bs[nb][bkr][bcq + 4]  = b1;
      *(float4*)&Bs[nb][bkr][bcq + 8]  = b2;
      *(float4*)&Bs[nb][bkr][bcq + 12] = b3;
    }
    __syncthreads();
  }

  #pragma unroll
  for (int i = 0; i < 8; i++) {
    float2 u0 = unpack2(acc[i][0]), u1 = unpack2(acc[i][1]);
    float2 u2 = unpack2(acc[i][2]), u3 = unpack2(acc[i][3]);
    float4 f0 = make_float4(u0.x, u0.y, u1.x, u1.y);
    float4 f1 = make_float4(u2.x, u2.y, u3.x, u3.y);
    if (EPI == 1) {
      f0.x = fmaxf(f0.x, 0.f); f0.y = fmaxf(f0.y, 0.f);
      f0.z = fmaxf(f0.z, 0.f); f0.w = fmaxf(f0.w, 0.f);
      f1.x = fmaxf(f1.x, 0.f); f1.y = fmaxf(f1.y, 0.f);
      f1.z = fmaxf(f1.z, 0.f); f1.w = fmaxf(f1.w, 0.f);
    }
    float* yp = &Y[(size_t)(bm0 + r0 + i) * NOUT + bn0 + c0];
    *(float4*)yp       = f0;
    *(float4*)(yp + 4) = f1;
  }
}

// ================ GEMM P: partial split-K, BM=32, BN=128, BK=16, 128 threads, 4x8 tile ================
// blockIdx.z = K-split (each handles KH rows of W starting at z*KH). No bias/epilogue.
// ATTN: A elements are the attention-combined outputs read from (po, ml) split pair.
template <int ATTN>
__global__ void __launch_bounds__(128) k_gemmP(
    const float* __restrict__ X,
    const float* __restrict__ po, const float* __restrict__ ml,
    int KK, int KH,
    const float* __restrict__ W,
    float* __restrict__ Yp) {
  __shared__ float As[2][16][32];
  __shared__ float Bs[2][16][128];
  const int t  = threadIdx.x;
  const int tx = t & 15, ty = t >> 4;
  const int bm0 = blockIdx.x * 32;
  const int z   = blockIdx.z;
  const int r0 = ty * 4, c0 = tx * 8;
  const int am = t >> 2,  akq = (t & 3) * 4;
  const int bkr = t >> 3, bcq = (t & 7) * 16;

  const int row = bm0 + am;
  const int kb  = z * KH + akq;

  // per-thread constants for the ATTN loader
  int bq_b = 0, bq_q = 0;
  if (ATTN) { bq_b = row >> 8; bq_q = row & 255; }

  u64 acc[4][4];
  #pragma unroll
  for (int i = 0; i < 4; i++) { acc[i][0]=0; acc[i][1]=0; acc[i][2]=0; acc[i][3]=0; }

  const float* Xp = X + (size_t)row * KK + kb;
  const float* Wp = W + (size_t)(z * KH + bkr) * 128 + bcq;
  const int NT = KH >> 4;

  // A loader: element chunk (row, kk..kk+3) — for ATTN, combine 2 attention splits.
  auto loadA = [&](int it) -> float4 {
    if (!ATTN) {
      return *(const float4*)(Xp + it * 16);
    } else {
      const int kk = kb + it * 16;      // global k in [0,128)
      const int h = kk >> 5, d4 = kk & 31;
      const int bhq = (bq_b * HH + h) * NN + bq_q;
      float2 m0 = *(const float2*)&ml[(size_t)bhq * 2];
      float2 m1 = *(const float2*)&ml[((size_t)BHQ + bhq) * 2];
      float M = fmaxf(m0.x, m1.x);
      float w0 = __expf(m0.x - M), w1 = __expf(m1.x - M);
      float inv = 1.f / (w0 * m0.y + w1 * m1.y);
      w0 *= inv; w1 *= inv;
      float4 p0 = *(const float4*)&po[((size_t)bhq) * 32 + d4];
      float4 p1 = *(const float4*)&po[((size_t)BHQ + bhq) * 32 + d4];
      return make_float4(w0 * p0.x + w1 * p1.x, w0 * p0.y + w1 * p1.y,
                         w0 * p0.z + w1 * p1.z, w0 * p0.w + w1 * p1.w);
    }
  };

  float4 a0 = loadA(0);
  float4 b0 = *(const float4*)Wp;
  float4 b1 = *(const float4*)(Wp + 4);
  float4 b2 = *(const float4*)(Wp + 8);
  float4 b3 = *(const float4*)(Wp + 12);
  {
    As[0][akq + 0][am] = a0.x; As[0][akq + 1][am] = a0.y;
    As[0][akq + 2][am] = a0.z; As[0][akq + 3][am] = a0.w;
    *(float4*)&Bs[0][bkr][bcq]      = b0;
    *(float4*)&Bs[0][bkr][bcq + 4]  = b1;
    *(float4*)&Bs[0][bkr][bcq + 8]  = b2;
    *(float4*)&Bs[0][bkr][bcq + 12] = b3;
  }
  __syncthreads();

  for (int it = 0; it < NT; it++) {
    const int buf = it & 1;
    if (it + 1 < NT) {
      a0 = loadA(it + 1);
      const float* wp = Wp + (size_t)(it + 1) * 16 * 128;
      b0 = *(const float4*)wp;        b1 = *(const float4*)(wp + 4);
      b2 = *(const float4*)(wp + 8);  b3 = *(const float4*)(wp + 12);
    }
    #pragma unroll
    for (int k = 0; k < 16; k++) {
      float4 av = *(const float4*)&As[buf][k][r0];
      ulonglong2 bv0 = *(const ulonglong2*)&Bs[buf][k][c0];
      ulonglong2 bv1 = *(const ulonglong2*)&Bs[buf][k][c0 + 4];
      u64 pa0 = pack2(av.x, av.x);
      u64 pa1 = pack2(av.y, av.y);
      u64 pa2 = pack2(av.z, av.z);
      u64 pa3 = pack2(av.w, av.w);
      ffma2(acc[0][0], pa0, bv0.x); ffma2(acc[0][1], pa0, bv0.y);
      ffma2(acc[0][2], pa0, bv1.x); ffma2(acc[0][3], pa0, bv1.y);
      ffma2(acc[1][0], pa1, bv0.x); ffma2(acc[1][1], pa1, bv0.y);
      ffma2(acc[1][2], pa1, bv1.x); ffma2(acc[1][3], pa1, bv1.y);
      ffma2(acc[2][0], pa2, bv0.x); ffma2(acc[2][1], pa2, bv0.y);
      ffma2(acc[2][2], pa2, bv1.x); ffma2(acc[2][3], pa2, bv1.y);
      ffma2(acc[3][0], pa3, bv0.x); ffma2(acc[3][1], pa3, bv0.y);
      ffma2(acc[3][2], pa3, bv1.x); ffma2(acc[3][3], pa3, bv1.y);
    }
    if (it + 1 < NT) {
      const int nb = buf ^ 1;
      As[nb][akq + 0][am] = a0.x; As[nb][akq + 1][am] = a0.y;
      As[nb][akq + 2][am] = a0.z; As[nb][akq + 3][am] = a0.w;
      *(float4*)&Bs[nb][bkr][bcq]      = b0;
      *(float4*)&Bs[nb][bkr][bcq + 4]  = b1;
      *(float4*)&Bs[nb][bkr][bcq + 8]  = b2;
      *(float4*)&Bs[nb][bkr][bcq + 12] = b3;
    }
    __syncthreads();
  }

  float* yp = Yp + (size_t)z * (ROWS * DD) + (size_t)(bm0 + r0) * DD + c0;
  #pragma unroll
  for (int i = 0; i < 4; i++) {
    float2 u0 = unpack2(acc[i][0]), u1 = unpack2(acc[i][1]);
    float2 u2 = unpack2(acc[i][2]), u3 = unpack2(acc[i][3]);
    *(float4*)(yp + (size_t)i * DD)     = make_float4(u0.x, u0.y, u1.x, u1.y);
    *(float4*)(yp + (size_t)i * DD + 4) = make_float4(u2.x, u2.y, u3.x, u3.y);
  }
}

// ================ combine partials + bias (+relu | +res) + LayerNorm; warp per row ================
template <int RELU, int RES, int TWO>
__global__ void __launch_bounds__(256) k_combln(
    const float* __restrict__ p0, const float* __restrict__ p1,
    const float* __restrict__ bias, const float* __restrict__ res,
    const float* __restrict__ g, const float* __restrict__ beta,
    float* __restrict__ Y) {
  const int row = blockIdx.x * 8 + (threadIdx.x >> 5);
  const int lane = threadIdx.x & 31;
  const int c0 = lane * 4;
  const size_t off = (size_t)row * DD + c0;

  float4 v = *(const float4*)&p0[off];
  if (TWO) {
    float4 w = *(const float4*)&p1[off];
    v.x += w.x; v.y += w.y; v.z += w.z; v.w += w.w;
  }
  float4 bv = *(const float4*)&bias[c0];
  v.x += bv.x; v.y += bv.y; v.z += bv.z; v.w += bv.w;
  if (RELU) {
    v.x = fmaxf(v.x, 0.f); v.y = fmaxf(v.y, 0.f);
    v.z = fmaxf(v.z, 0.f); v.w = fmaxf(v.w, 0.f);
  }
  if (RES) {
    float4 r = *(const float4*)&res[off];
    v.x += r.x; v.y += r.y; v.z += r.z; v.w += r.w;
  }
  float s  = v.x + v.y + v.z + v.w;
  float s2 = v.x * v.x + v.y * v.y + v.z * v.z + v.w * v.w;
  #pragma unroll
  for (int o = 16; o; o >>= 1) {
    s  += __shfl_xor_sync(0xffffffffu, s,  o);
    s2 += __shfl_xor_sync(0xffffffffu, s2, o);
  }
  float mu = s * (1.f / 128.f);
  float var = s2 * (1.f / 128.f) - mu * mu;
  float rstd = rsqrtf(var + EPSF);
  float4 gv = *(const float4*)&g[c0];
  float4 ev = *(const float4*)&beta[c0];
  *(float4*)&Y[off] = make_float4(
      (v.x - mu) * rstd * gv.x + ev.x, (v.y - mu) * rstd * gv.y + ev.y,
      (v.z - mu) * rstd * gv.z + ev.z, (v.w - mu) * rstd * gv.w + ev.w);
}

// ================ attention: split-K partials (SPLITS=2, 128 keys each) ================
__global__ void __launch_bounds__(256) k_attn_part(const float* __restrict__ qkv,
                                                   float* __restrict__ po,
                                                   float* __restrict__ ml) {
  const int split = blockIdx.x, h = blockIdx.y, b = blockIdx.z;
  const int q = threadIdx.x;  // 256
  __shared__ float Ks[128][DHH], Vs[128][DHH];
  const float* base = qkv + (size_t)b * NN * (3 * DD);
  const int hoff = h * DHH;
  const int kbase = split * 128;

  for (int c = threadIdx.x; c < 128 * DHH / 4; c += 256) {
    int r = c >> 3, d4 = (c & 7) << 2;
    *(float4*)&Ks[r][d4] = *(const float4*)&base[(size_t)(kbase + r) * (3 * DD) + DD     + hoff + d4];
    *(float4*)&Vs[r][d4] = *(const float4*)&base[(size_t)(kbase + r) * (3 * DD) + 2 * DD + hoff + d4];
  }
  u64 qp[16];
  {
    const ulonglong2* qptr = (const ulonglong2*)(base + (size_t)q * (3 * DD) + hoff);
    #pragma unroll
    for (int i = 0; i < 8; i++) { ulonglong2 u = qptr[i]; qp[2*i] = u.x; qp[2*i+1] = u.y; }
  }
  __syncthreads();

  float m = -1e30f, l = 0.f;
  u64 op[16];
  #pragma unroll
  for (int i = 0; i < 16; i++) op[i] = 0ull;
  const float scale = 0.17677669529663687f;

  for (int k = 0; k < 128; k++) {
    const ulonglong2* kr = (const ulonglong2*)&Ks[k][0];
    u64 sp0 = 0, sp1 = 0, sp2 = 0, sp3 = 0;
    #pragma unroll
    for (int i = 0; i < 4; i++) {
      ulonglong2 ka = kr[2*i], kb = kr[2*i+1];
      ffma2(sp0, qp[4*i],     ka.x);
      ffma2(sp1, qp[4*i + 1], ka.y);
      ffma2(sp2, qp[4*i + 2], kb.x);
      ffma2(sp3, qp[4*i + 3], kb.y);
    }
    float2 u0 = unpack2(sp0), u1 = unpack2(sp1), u2 = unpack2(sp2), u3 = unpack2(sp3);
    float s = ((u0.x + u0.y) + (u1.x + u1.y)) + ((u2.x + u2.y) + (u3.x + u3.y));
    s *= scale;
    const ulonglong2* vr = (const ulonglong2*)&Vs[k][0];
    if (s > m) {
      float c = __expf(m - s);
      m = s;
      l = l * c + 1.f;
      u64 cp = pack2(c, c);
      #pragma unroll
      for (int i = 0; i < 8; i++) {
        ulonglong2 vv = vr[i];
        op[2*i]     = ffma2_o(op[2*i],     cp, vv.x);
        op[2*i + 1] = ffma2_o(op[2*i + 1], cp, vv.y);
      }
    } else {
      float p = __expf(s - m);
      l += p;
      u64 pp = pack2(p, p);
      #pragma unroll
      for (int i = 0; i < 8; i++) {
        ulonglong2 vv = vr[i];
        ffma2(op[2*i],     pp, vv.x);
        ffma2(op[2*i + 1], pp, vv.y);
      }
    }
  }

  const int bhq = (b * HH + h) * NN + q;
  float* pop = po + ((size_t)split * BHQ + bhq) * 32;
  #pragma unroll
  for (int i = 0; i < 8; i++) {
    float2 a = unpack2(op[2*i]), c = unpack2(op[2*i + 1]);
    *(float4*)&pop[4*i] = make_float4(a.x, a.y, c.x, c.y);
  }
  *(float2*)&ml[((size_t)split * BHQ + bhq) * 2] = make_float2(m, l);
}

// ================ pair kernel: 64i x 64j per block, 4x4 pairs per thread ================
#define SP 132  // padded row stride (floats)
__global__ void __launch_bounds__(256) k_pair(const float* __restrict__ w2,
                                              const float* __restrict__ b2,
                                              float* __restrict__ out) {
  extern __shared__ float sm[];
  float* smA = sm;                   // 64*SP
  float* smB = sm + 64 * SP;         // 64*SP
  float* smw = sm + 128 * SP;        // 128
  const int b  = blockIdx.z;
  const int i0 = blockIdx.x * 64;
  const int j0 = blockIdx.y * 64;
  const int t  = threadIdx.x;  // 256
  const int jx = t & 15, iy = t >> 4;

  {
    const float* Ab = g_A  + ((size_t)(b * NN + i0)) * DD;
    const float* Bb = g_Bm + ((size_t)(b * NN + j0)) * DD;
    for (int idx = t; idx < 64 * 32; idx += 256) {
      int r = idx >> 5, dq = (idx & 31) << 2;
      *(float4*)&smA[r * SP + dq] = *(const float4*)&Ab[(size_t)r * DD + dq];
      *(float4*)&smB[r * SP + dq] = *(const float4*)&Bb[(size_t)r * DD + dq];
    }
    if (t < 32) *(float4*)&smw[t * 4] = *(const float4*)&w2[t * 4];
  }
  __syncthreads();

  const int ibl = iy * 4;
  u64 acc[4][4];
  #pragma unroll
  for (int ii = 0; ii < 4; ii++)
    #pragma unroll
    for (int jj = 0; jj < 4; jj++) acc[ii][jj] = 0ull;

  for (int d = 0; d < DD; d += 4) {
    ulonglong2 wv = *(const ulonglong2*)&smw[d];
    ulonglong2 av[4], bv[4];
    #pragma unroll
    for (int ii = 0; ii < 4; ii++) av[ii] = *(const ulonglong2*)&smA[(ibl + ii) * SP + d];
    #pragma unroll
    for (int jj = 0; jj < 4; jj++) bv[jj] = *(const ulonglong2*)&smB[(jx + 16 * jj) * SP + d];
    #pragma unroll
    for (int ii = 0; ii < 4; ii++) {
      #pragma unroll
      for (int jj = 0; jj < 4; jj++) {
        u64 s0 = relu2(add2(av[ii].x, bv[jj].x));
        ffma2(acc[ii][jj], s0, wv.x);
        u64 s1 = relu2(add2(av[ii].y, bv[jj].y));
        ffma2(acc[ii][jj], s1, wv.y);
      }
    }
  }

  const float b2v = b2[0];
  float* outb = out + (size_t)b * PP;
  #pragma unroll
  for (int ii = 0; ii < 4; ii++) {
    const int i = i0 + ibl + ii;
    #pragma unroll
    for (int jj = 0; jj < 4; jj++) {
      const int j = j0 + jx + 16 * jj;
      if (j != i) {
        float2 u = unpack2(acc[ii][jj]);
        outb[i * (NN - 1) + j - (j > i ? 1 : 0)] = u.x + u.y + b2v;
      }
    }
  }
}

// ================ host ================
extern "C" void kernel_launch(void* const* d_in, const int* in_sizes, int n_in,
                              void* d_out, int out_size) {
  const float* agents   = (const float*)d_in[0];
  const float* enc_w    = (const float*)d_in[1];
  const float* enc_b    = (const float*)d_in[2];
  const float* enc_g    = (const float*)d_in[3];
  const float* enc_beta = (const float*)d_in[4];
  const float* qkv_w    = (const float*)d_in[5];
  const float* qkv_b    = (const float*)d_in[6];
  const float* attn_ow  = (const float*)d_in[7];
  const float* attn_ob  = (const float*)d_in[8];
  const float* ln1_g    = (const float*)d_in[9];
  const float* ln1_b    = (const float*)d_in[10];
  const float* ffn_w1   = (const float*)d_in[11];
  const float* ffn_b1   = (const float*)d_in[12];
  const float* ffn_w2   = (const float*)d_in[13];
  const float* ffn_b2   = (const float*)d_in[14];
  const float* ln2_g    = (const float*)d_in[15];
  const float* ln2_b    = (const float*)d_in[16];
  const float* rel_w1   = (const float*)d_in[17];
  const float* rel_b1   = (const float*)d_in[18];
  const float* rel_w2   = (const float*)d_in[19];
  const float* rel_b2   = (const float*)d_in[20];
  float* out = (float*)d_out;

  float *px, *pqkv, *pffn, *pA, *pBm;
  cudaGetSymbolAddress((void**)&px,    g_x);
  cudaGetSymbolAddress((void**)&pqkv,  g_qkv);
  cudaGetSymbolAddress((void**)&pffn,  g_ffn);
  cudaGetSymbolAddress((void**)&pA,    g_A);
  cudaGetSymbolAddress((void**)&pBm,   g_Bm);
  float* ppart = pqkv;             // split-K partials (2 * ROWS*DD floats <= ROWS*3*DD)
  float* ppo   = pffn;             // attention partial outputs
  float* pml   = pA;               // attention partial (m,l)

  const int pair_smem = (128 * SP + 128) * sizeof(float);  // ~66KB
  cudaFuncSetAttribute(k_pair, cudaFuncAttributeMaxDynamicSharedMemorySize, pair_smem);

  // encoder: relu(agents @ enc_w + b) -> LN  (K=64, single "split")
  k_gemmP<0><<<dim3(ROWS / 32, 1, 1), 128>>>(agents, nullptr, nullptr, FF, FF,
                                             enc_w, ppart);
  k_combln<1, 0, 0><<<ROWS / 8, 256>>>(ppart, nullptr, enc_b, nullptr,
                                       enc_g, enc_beta, px);

  for (int l = 0; l < LL; l++) {
    // qkv
    k_gemmA<0><<<dim3(ROWS / 64, 3), 128>>>(px, DD, qkv_w + (size_t)l * DD * 3 * DD,
                                            3 * DD, qkv_b + (size_t)l * 3 * DD, pqkv, nullptr);
    // attention partials
    k_attn_part<<<dim3(SPLITS, HH, BB), 256>>>(pqkv, ppo, pml);
    // proj (attention combine fused into A-load), split-K x2 -> partials
    k_gemmP<1><<<dim3(ROWS / 32, 1, 2), 128>>>(nullptr, ppo, pml, DD, DD / 2,
                                               attn_ow + (size_t)l * DD * DD, ppart);
    k_combln<0, 1, 1><<<ROWS / 8, 256>>>(ppart, ppart + (size_t)ROWS * DD,
                                         attn_ob + (size_t)l * DD, px,
                                         ln1_g + (size_t)l * DD, ln1_b + (size_t)l * DD, px);
    // ffn1
    k_gemmA<1><<<dim3(ROWS / 64, 4), 128>>>(px, DD, ffn_w1 + (size_t)l * DD * DFF_,
                                            DFF_, ffn_b1 + (size_t)l * DFF_, pffn, nullptr);
    // ffn2 split-K x2 -> partials
    k_gemmP<0><<<dim3(ROWS / 32, 1, 2), 128>>>(pffn, nullptr, nullptr, DFF_, DFF_ / 2,
                                               ffn_w2 + (size_t)l * DFF_ * DD, ppart);
    k_combln<0, 1, 1><<<ROWS / 8, 256>>>(ppart, ppart + (size_t)ROWS * DD,
                                         ffn_b2 + (size_t)l * DD, px,
                                         ln2_g + (size_t)l * DD, ln2_b + (size_t)l * DD, px);
  }

  // pair precompute: A = x@W1[:D]+b1 ; Bm = x@W1[D:]
  k_gemmA<5><<<dim3(ROWS / 64, 1, 2), 128>>>(px, DD, rel_w1, DD, rel_b1, pA, pBm);

  k_pair<<<dim3(NN / 64, NN / 64, BB), 256, pair_smem>>>(rel_w2, rel_b2, out);
}

// round 7
// speedup vs baseline: 1.3162x; 1.0886x over previous
#include <cuda_runtime.h>

#define BB 16
#define NN 256
#define FF 64
#define DD 128
#define HH 4
#define DHH 32
#define DFF_ 512
#define LL 2
#define ROWS (BB*NN)     // 4096
#define PP (NN*(NN-1))   // 65280
#define EPSF 1e-5f
#define SPLITS 4
#define BHQ (BB*HH*NN)   // 16384

// ---------------- scratch ----------------
__device__ float g_x[ROWS*DD];
__device__ float g_qkv[ROWS*3*DD];    // qkv; later reused for GEMM split-K partials
__device__ float g_ffn[ROWS*DFF_];    // ffn1 acts; also attention po scratch (SPLITS*BHQ*32 = 2097152 exact)
__device__ float g_A[ROWS*DD];        // pairpre A; also attention l scratch (SPLITS*BHQ = 65536)
__device__ float g_Bm[ROWS*DD];

typedef unsigned long long u64;

__device__ __forceinline__ u64 pack2(float x, float y) {
  u64 r; asm("mov.b64 %0, {%1, %2};" : "=l"(r) : "f"(x), "f"(y)); return r;
}
__device__ __forceinline__ float2 unpack2(u64 v) {
  float2 r; asm("mov.b64 {%0, %1}, %2;" : "=f"(r.x), "=f"(r.y) : "l"(v)); return r;
}
__device__ __forceinline__ void ffma2(u64 &d, u64 a, u64 b) {
  asm("fma.rn.f32x2 %0, %1, %2, %0;" : "+l"(d) : "l"(a), "l"(b));
}
__device__ __forceinline__ u64 add2(u64 a, u64 b) {
  u64 o; asm("add.rn.f32x2 %0, %1, %2;" : "=l"(o) : "l"(a), "l"(b)); return o;
}
__device__ __forceinline__ u64 relu2(u64 v) {
  float2 f = unpack2(v);
  return pack2(fmaxf(f.x, 0.f), fmaxf(f.y, 0.f));
}

// ================ GEMM A: BM=64, BN=128, BK=16, 128 threads, 8x8 thread tile ================
// EPI: 0 = +bias ; 1 = +bias,relu ; 5 = pairpre dual (blockIdx.z selects W half / output)
template <int EPI>
__global__ void __launch_bounds__(128) k_gemmA(
    const float* __restrict__ X, int KK,
    const float* __restrict__ W, int NOUT,
    const float* __restrict__ bias,
    float* __restrict__ Y, float* __restrict__ Y2) {
  __shared__ float As[2][16][64];
  __shared__ float Bs[2][16][128];
  const int t  = threadIdx.x;
  const int tx = t & 15, ty = t >> 4;
  const int bm0 = blockIdx.x * 64, bn0 = blockIdx.y * 128;
  const int r0 = ty * 8, c0 = tx * 8;
  const int am = t >> 1,  akq = (t & 1) * 8;
  const int bkr = t >> 3, bcq = (t & 7) * 16;

  if (EPI == 5) {
    if (blockIdx.z) { W += (size_t)KK * NOUT; Y = Y2; bias = nullptr; }
  }

  u64 acc[8][4];
  {
    u64 i0 = 0, i1 = 0, i2 = 0, i3 = 0;
    if (EPI != 5 || bias) {
      if (bias) {
        float4 bv0 = *(const float4*)&bias[bn0 + c0];
        float4 bv1 = *(const float4*)&bias[bn0 + c0 + 4];
        i0 = pack2(bv0.x, bv0.y); i1 = pack2(bv0.z, bv0.w);
        i2 = pack2(bv1.x, bv1.y); i3 = pack2(bv1.z, bv1.w);
      }
    }
    #pragma unroll
    for (int i = 0; i < 8; i++) { acc[i][0]=i0; acc[i][1]=i1; acc[i][2]=i2; acc[i][3]=i3; }
  }

  const float* Xp = X + (size_t)(bm0 + am) * KK + akq;
  const float* Wp = W + (size_t)bkr * NOUT + bn0 + bcq;
  const int NT = KK >> 4;

  float4 a0 = *(const float4*)Xp;
  float4 a1 = *(const float4*)(Xp + 4);
  float4 b0 = *(const float4*)Wp;
  float4 b1 = *(const float4*)(Wp + 4);
  float4 b2 = *(const float4*)(Wp + 8);
  float4 b3 = *(const float4*)(Wp + 12);
  {
    As[0][akq + 0][am] = a0.x; As[0][akq + 1][am] = a0.y;
    As[0][akq + 2][am] = a0.z; As[0][akq + 3][am] = a0.w;
    As[0][akq + 4][am] = a1.x; As[0][akq + 5][am] = a1.y;
    As[0][akq + 6][am] = a1.z; As[0][akq + 7][am] = a1.w;
    *(float4*)&Bs[0][bkr][bcq]      = b0;
    *(float4*)&Bs[0][bkr][bcq + 4]  = b1;
    *(float4*)&Bs[0][bkr][bcq + 8]  = b2;
    *(float4*)&Bs[0][bkr][bcq + 12] = b3;
  }
  __syncthreads();

  for (int it = 0; it < NT; it++) {
    const int buf = it & 1;
    if (it + 1 < NT) {
      const float* xp = Xp + (it + 1) * 16;
      a0 = *(const float4*)xp; a1 = *(const float4*)(xp + 4);
      const float* wp = Wp + (size_t)(it + 1) * 16 * NOUT;
      b0 = *(const float4*)wp;        b1 = *(const float4*)(wp + 4);
      b2 = *(const float4*)(wp + 8);  b3 = *(const float4*)(wp + 12);
    }
    #pragma unroll
    for (int k = 0; k < 16; k++) {
      float4 av0 = *(const float4*)&As[buf][k][r0];
      float4 av1 = *(const float4*)&As[buf][k][r0 + 4];
      ulonglong2 bv0 = *(const ulonglong2*)&Bs[buf][k][c0];
      ulonglong2 bv1 = *(const ulonglong2*)&Bs[buf][k][c0 + 4];
      u64 pa[8];
      pa[0] = pack2(av0.x, av0.x); pa[1] = pack2(av0.y, av0.y);
      pa[2] = pack2(av0.z, av0.z); pa[3] = pack2(av0.w, av0.w);
      pa[4] = pack2(av1.x, av1.x); pa[5] = pack2(av1.y, av1.y);
      pa[6] = pack2(av1.z, av1.z); pa[7] = pack2(av1.w, av1.w);
      #pragma unroll
      for (int i = 0; i < 8; i++) {
        ffma2(acc[i][0], pa[i], bv0.x);
        ffma2(acc[i][1], pa[i], bv0.y);
        ffma2(acc[i][2], pa[i], bv1.x);
        ffma2(acc[i][3], pa[i], bv1.y);
      }
    }
    if (it + 1 < NT) {
      const int nb = buf ^ 1;
      As[nb][akq + 0][am] = a0.x; As[nb][akq + 1][am] = a0.y;
      As[nb][akq + 2][am] = a0.z; As[nb][akq + 3][am] = a0.w;
      As[nb][akq + 4][am] = a1.x; As[nb][akq + 5][am] = a1.y;
      As[nb][akq + 6][am] = a1.z; As[nb][akq + 7][am] = a1.w;
      *(float4*)&Bs[nb][bkr][bcq]      = b0;
      *(float4*)&Bs[nb][bkr][bcq + 4]  = b1;
      *(float4*)&Bs[nb][bkr][bcq + 8]  = b2;
      *(float4*)&Bs[nb][bkr][bcq + 12] = b3;
    }
    __syncthreads();
  }

  #pragma unroll
  for (int i = 0; i < 8; i++) {
    float2 u0 = unpack2(acc[i][0]), u1 = unpack2(acc[i][1]);
    float2 u2 = unpack2(acc[i][2]), u3 = unpack2(acc[i][3]);
    float4 f0 = make_float4(u0.x, u0.y, u1.x, u1.y);
    float4 f1 = make_float4(u2.x, u2.y, u3.x, u3.y);
    if (EPI == 1) {
      f0.x = fmaxf(f0.x, 0.f); f0.y = fmaxf(f0.y, 0.f);
      f0.z = fmaxf(f0.z, 0.f); f0.w = fmaxf(f0.w, 0.f);
      f1.x = fmaxf(f1.x, 0.f); f1.y = fmaxf(f1.y, 0.f);
      f1.z = fmaxf(f1.z, 0.f); f1.w = fmaxf(f1.w, 0.f);
    }
    float* yp = &Y[(size_t)(bm0 + r0 + i) * NOUT + bn0 + c0];
    *(float4*)yp       = f0;
    *(float4*)(yp + 4) = f1;
  }
}

// ================ GEMM P: partial split-K, BM=32, BN=128, BK=16, 128 threads, 4x8 tile ================
// blockIdx.z = K-split. ATTN: A elements are attention-combined outputs from (po, l) partials.
template <int ATTN>
__global__ void __launch_bounds__(128) k_gemmP(
    const float* __restrict__ X,
    const float* __restrict__ po, const float* __restrict__ pl,
    int KK, int KH,
    const float* __restrict__ W,
    float* __restrict__ Yp) {
  __shared__ float As[2][16][32];
  __shared__ float Bs[2][16][128];
  const int t  = threadIdx.x;
  const int tx = t & 15, ty = t >> 4;
  const int bm0 = blockIdx.x * 32;
  const int z   = blockIdx.z;
  const int r0 = ty * 4, c0 = tx * 8;
  const int am = t >> 2,  akq = (t & 3) * 4;
  const int bkr = t >> 3, bcq = (t & 7) * 16;

  const int row = bm0 + am;
  const int kb  = z * KH + akq;

  int bq_b = 0, bq_q = 0;
  if (ATTN) { bq_b = row >> 8; bq_q = row & 255; }

  u64 acc[4][4];
  #pragma unroll
  for (int i = 0; i < 4; i++) { acc[i][0]=0; acc[i][1]=0; acc[i][2]=0; acc[i][3]=0; }

  const float* Xp = X + (size_t)row * KK + kb;
  const float* Wp = W + (size_t)(z * KH + bkr) * 128 + bcq;
  const int NT = KH >> 4;

  auto loadA = [&](int it) -> float4 {
    if (!ATTN) {
      return *(const float4*)(Xp + it * 16);
    } else {
      const int kk = kb + it * 16;      // global k in [0,128)
      const int h = kk >> 5, d4 = kk & 31;
      const int bhq = (bq_b * HH + h) * NN + bq_q;
      float lsum = pl[bhq] + pl[BHQ + bhq] + pl[2 * BHQ + bhq] + pl[3 * BHQ + bhq];
      float inv = 1.f / lsum;
      float4 p0 = *(const float4*)&po[((size_t)bhq) * 32 + d4];
      float4 p1 = *(const float4*)&po[((size_t)BHQ + bhq) * 32 + d4];
      float4 p2 = *(const float4*)&po[((size_t)2 * BHQ + bhq) * 32 + d4];
      float4 p3 = *(const float4*)&po[((size_t)3 * BHQ + bhq) * 32 + d4];
      return make_float4((p0.x + p1.x + p2.x + p3.x) * inv,
                         (p0.y + p1.y + p2.y + p3.y) * inv,
                         (p0.z + p1.z + p2.z + p3.z) * inv,
                         (p0.w + p1.w + p2.w + p3.w) * inv);
    }
  };

  float4 a0 = loadA(0);
  float4 b0 = *(const float4*)Wp;
  float4 b1 = *(const float4*)(Wp + 4);
  float4 b2 = *(const float4*)(Wp + 8);
  float4 b3 = *(const float4*)(Wp + 12);
  {
    As[0][akq + 0][am] = a0.x; As[0][akq + 1][am] = a0.y;
    As[0][akq + 2][am] = a0.z; As[0][akq + 3][am] = a0.w;
    *(float4*)&Bs[0][bkr][bcq]      = b0;
    *(float4*)&Bs[0][bkr][bcq + 4]  = b1;
    *(float4*)&Bs[0][bkr][bcq + 8]  = b2;
    *(float4*)&Bs[0][bkr][bcq + 12] = b3;
  }
  __syncthreads();

  for (int it = 0; it < NT; it++) {
    const int buf = it & 1;
    if (it + 1 < NT) {
      a0 = loadA(it + 1);
      const float* wp = Wp + (size_t)(it + 1) * 16 * 128;
      b0 = *(const float4*)wp;        b1 = *(const float4*)(wp + 4);
      b2 = *(const float4*)(wp + 8);  b3 = *(const float4*)(wp + 12);
    }
    #pragma unroll
    for (int k = 0; k < 16; k++) {
      float4 av = *(const float4*)&As[buf][k][r0];
      ulonglong2 bv0 = *(const ulonglong2*)&Bs[buf][k][c0];
      ulonglong2 bv1 = *(const ulonglong2*)&Bs[buf][k][c0 + 4];
      u64 pa0 = pack2(av.x, av.x);
      u64 pa1 = pack2(av.y, av.y);
      u64 pa2 = pack2(av.z, av.z);
      u64 pa3 = pack2(av.w, av.w);
      ffma2(acc[0][0], pa0, bv0.x); ffma2(acc[0][1], pa0, bv0.y);
      ffma2(acc[0][2], pa0, bv1.x); ffma2(acc[0][3], pa0, bv1.y);
      ffma2(acc[1][0], pa1, bv0.x); ffma2(acc[1][1], pa1, bv0.y);
      ffma2(acc[1][2], pa1, bv1.x); ffma2(acc[1][3], pa1, bv1.y);
      ffma2(acc[2][0], pa2, bv0.x); ffma2(acc[2][1], pa2, bv0.y);
      ffma2(acc[2][2], pa2, bv1.x); ffma2(acc[2][3], pa2, bv1.y);
      ffma2(acc[3][0], pa3, bv0.x); ffma2(acc[3][1], pa3, bv0.y);
      ffma2(acc[3][2], pa3, bv1.x); ffma2(acc[3][3], pa3, bv1.y);
    }
    if (it + 1 < NT) {
      const int nb = buf ^ 1;
      As[nb][akq + 0][am] = a0.x; As[nb][akq + 1][am] = a0.y;
      As[nb][akq + 2][am] = a0.z; As[nb][akq + 3][am] = a0.w;
      *(float4*)&Bs[nb][bkr][bcq]      = b0;
      *(float4*)&Bs[nb][bkr][bcq + 4]  = b1;
      *(float4*)&Bs[nb][bkr][bcq + 8]  = b2;
      *(float4*)&Bs[nb][bkr][bcq + 12] = b3;
    }
    __syncthreads();
  }

  float* yp = Yp + (size_t)z * (ROWS * DD) + (size_t)(bm0 + r0) * DD + c0;
  #pragma unroll
  for (int i = 0; i < 4; i++) {
    float2 u0 = unpack2(acc[i][0]), u1 = unpack2(acc[i][1]);
    float2 u2 = unpack2(acc[i][2]), u3 = unpack2(acc[i][3]);
    *(float4*)(yp + (size_t)i * DD)     = make_float4(u0.x, u0.y, u1.x, u1.y);
    *(float4*)(yp + (size_t)i * DD + 4) = make_float4(u2.x, u2.y, u3.x, u3.y);
  }
}

// ================ combine partials + bias (+relu | +res) + LayerNorm; warp per row ================
template <int RELU, int RES, int TWO>
__global__ void __launch_bounds__(256) k_combln(
    const float* __restrict__ p0, const float* __restrict__ p1,
    const float* __restrict__ bias, const float* __restrict__ res,
    const float* __restrict__ g, const float* __restrict__ beta,
    float* __restrict__ Y) {
  const int row = blockIdx.x * 8 + (threadIdx.x >> 5);
  const int lane = threadIdx.x & 31;
  const int c0 = lane * 4;
  const size_t off = (size_t)row * DD + c0;

  float4 v = *(const float4*)&p0[off];
  if (TWO) {
    float4 w = *(const float4*)&p1[off];
    v.x += w.x; v.y += w.y; v.z += w.z; v.w += w.w;
  }
  float4 bv = *(const float4*)&bias[c0];
  v.x += bv.x; v.y += bv.y; v.z += bv.z; v.w += bv.w;
  if (RELU) {
    v.x = fmaxf(v.x, 0.f); v.y = fmaxf(v.y, 0.f);
    v.z = fmaxf(v.z, 0.f); v.w = fmaxf(v.w, 0.f);
  }
  if (RES) {
    float4 r = *(const float4*)&res[off];
    v.x += r.x; v.y += r.y; v.z += r.z; v.w += r.w;
  }
  float s  = v.x + v.y + v.z + v.w;
  float s2 = v.x * v.x + v.y * v.y + v.z * v.z + v.w * v.w;
  #pragma unroll
  for (int o = 16; o; o >>= 1) {
    s  += __shfl_xor_sync(0xffffffffu, s,  o);
    s2 += __shfl_xor_sync(0xffffffffu, s2, o);
  }
  float mu = s * (1.f / 128.f);
  float var = s2 * (1.f / 128.f) - mu * mu;
  float rstd = rsqrtf(var + EPSF);
  float4 gv = *(const float4*)&g[c0];
  float4 ev = *(const float4*)&beta[c0];
  *(float4*)&Y[off] = make_float4(
      (v.x - mu) * rstd * gv.x + ev.x, (v.y - mu) * rstd * gv.y + ev.y,
      (v.z - mu) * rstd * gv.z + ev.z, (v.w - mu) * rstd * gv.w + ev.w);
}

// ================ attention: branch-free split-K partials (SPLITS=4, 64 keys each) ================
// Scores are tiny (|s| < ~5) so softmax without max-subtraction is exact: store
// unnormalized o = sum(exp(s)*v) and l = sum(exp(s)) per split.
__global__ void __launch_bounds__(256) k_attn_part(const float* __restrict__ qkv,
                                                   float* __restrict__ po,
                                                   float* __restrict__ pl) {
  const int split = blockIdx.x, h = blockIdx.y, b = blockIdx.z;
  const int q = threadIdx.x;  // 256
  __shared__ float Ks[64][DHH], Vs[64][DHH];
  const float* base = qkv + (size_t)b * NN * (3 * DD);
  const int hoff = h * DHH;
  const int kbase = split * 64;

  for (int c = threadIdx.x; c < 64 * DHH / 4; c += 256) {
    int r = c >> 3, d4 = (c & 7) << 2;
    *(float4*)&Ks[r][d4] = *(const float4*)&base[(size_t)(kbase + r) * (3 * DD) + DD     + hoff + d4];
    *(float4*)&Vs[r][d4] = *(const float4*)&base[(size_t)(kbase + r) * (3 * DD) + 2 * DD + hoff + d4];
  }
  u64 qp[16];
  {
    const ulonglong2* qptr = (const ulonglong2*)(base + (size_t)q * (3 * DD) + hoff);
    #pragma unroll
    for (int i = 0; i < 8; i++) { ulonglong2 u = qptr[i]; qp[2*i] = u.x; qp[2*i+1] = u.y; }
  }
  __syncthreads();

  float l = 0.f;
  u64 op[16];
  #pragma unroll
  for (int i = 0; i < 16; i++) op[i] = 0ull;
  const float scale = 0.17677669529663687f;  // 1/sqrt(32)

  #pragma unroll 2
  for (int k = 0; k < 64; k++) {
    const ulonglong2* kr = (const ulonglong2*)&Ks[k][0];
    u64 sp0 = 0, sp1 = 0, sp2 = 0, sp3 = 0;
    #pragma unroll
    for (int i = 0; i < 4; i++) {
      ulonglong2 ka = kr[2*i], kb = kr[2*i+1];
      ffma2(sp0, qp[4*i],     ka.x);
      ffma2(sp1, qp[4*i + 1], ka.y);
      ffma2(sp2, qp[4*i + 2], kb.x);
      ffma2(sp3, qp[4*i + 3], kb.y);
    }
    u64 sr = add2(add2(sp0, sp1), add2(sp2, sp3));
    float2 u = unpack2(sr);
    float p = __expf((u.x + u.y) * scale);
    l += p;
    u64 pp = pack2(p, p);
    const ulonglong2* vr = (const ulonglong2*)&Vs[k][0];
    #pragma unroll
    for (int i = 0; i < 8; i++) {
      ulonglong2 vv = vr[i];
      ffma2(op[2*i],     pp, vv.x);
      ffma2(op[2*i + 1], pp, vv.y);
    }
  }

  const int bhq = (b * HH + h) * NN + q;
  float* pop = po + ((size_t)split * BHQ + bhq) * 32;
  #pragma unroll
  for (int i = 0; i < 8; i++) {
    float2 a = unpack2(op[2*i]), c = unpack2(op[2*i + 1]);
    *(float4*)&pop[4*i] = make_float4(a.x, a.y, c.x, c.y);
  }
  pl[(size_t)split * BHQ + bhq] = l;
}

// ================ pair kernel: 64i x 64j per block, 4x4 pairs per thread ================
#define SP 132  // padded row stride (floats)
__global__ void __launch_bounds__(256) k_pair(const float* __restrict__ w2,
                                              const float* __restrict__ b2,
                                              float* __restrict__ out) {
  extern __shared__ float sm[];
  float* smA = sm;                   // 64*SP
  float* smB = sm + 64 * SP;         // 64*SP
  float* smw = sm + 128 * SP;        // 128
  const int b  = blockIdx.z;
  const int i0 = blockIdx.x * 64;
  const int j0 = blockIdx.y * 64;
  const int t  = threadIdx.x;  // 256
  const int jx = t & 15, iy = t >> 4;

  {
    const float* Ab = g_A  + ((size_t)(b * NN + i0)) * DD;
    const float* Bb = g_Bm + ((size_t)(b * NN + j0)) * DD;
    for (int idx = t; idx < 64 * 32; idx += 256) {
      int r = idx >> 5, dq = (idx & 31) << 2;
      *(float4*)&smA[r * SP + dq] = *(const float4*)&Ab[(size_t)r * DD + dq];
      *(float4*)&smB[r * SP + dq] = *(const float4*)&Bb[(size_t)r * DD + dq];
    }
    if (t < 32) *(float4*)&smw[t * 4] = *(const float4*)&w2[t * 4];
  }
  __syncthreads();

  const int ibl = iy * 4;
  u64 acc[4][4];
  #pragma unroll
  for (int ii = 0; ii < 4; ii++)
    #pragma unroll
    for (int jj = 0; jj < 4; jj++) acc[ii][jj] = 0ull;

  for (int d = 0; d < DD; d += 4) {
    ulonglong2 wv = *(const ulonglong2*)&smw[d];
    ulonglong2 av[4], bv[4];
    #pragma unroll
    for (int ii = 0; ii < 4; ii++) av[ii] = *(const ulonglong2*)&smA[(ibl + ii) * SP + d];
    #pragma unroll
    for (int jj = 0; jj < 4; jj++) bv[jj] = *(const ulonglong2*)&smB[(jx + 16 * jj) * SP + d];
    #pragma unroll
    for (int ii = 0; ii < 4; ii++) {
      #pragma unroll
      for (int jj = 0; jj < 4; jj++) {
        u64 s0 = relu2(add2(av[ii].x, bv[jj].x));
        ffma2(acc[ii][jj], s0, wv.x);
        u64 s1 = relu2(add2(av[ii].y, bv[jj].y));
        ffma2(acc[ii][jj], s1, wv.y);
      }
    }
  }

  const float b2v = b2[0];
  float* outb = out + (size_t)b * PP;
  #pragma unroll
  for (int ii = 0; ii < 4; ii++) {
    const int i = i0 + ibl + ii;
    #pragma unroll
    for (int jj = 0; jj < 4; jj++) {
      const int j = j0 + jx + 16 * jj;
      if (j != i) {
        float2 u = unpack2(acc[ii][jj]);
        outb[i * (NN - 1) + j - (j > i ? 1 : 0)] = u.x + u.y + b2v;
      }
    }
  }
}

// ================ host ================
extern "C" void kernel_launch(void* const* d_in, const int* in_sizes, int n_in,
                              void* d_out, int out_size) {
  const float* agents   = (const float*)d_in[0];
  const float* enc_w    = (const float*)d_in[1];
  const float* enc_b    = (const float*)d_in[2];
  const float* enc_g    = (const float*)d_in[3];
  const float* enc_beta = (const float*)d_in[4];
  const float* qkv_w    = (const float*)d_in[5];
  const float* qkv_b    = (const float*)d_in[6];
  const float* attn_ow  = (const float*)d_in[7];
  const float* attn_ob  = (const float*)d_in[8];
  const float* ln1_g    = (const float*)d_in[9];
  const float* ln1_b    = (const float*)d_in[10];
  const float* ffn_w1   = (const float*)d_in[11];
  const float* ffn_b1   = (const float*)d_in[12];
  const float* ffn_w2   = (const float*)d_in[13];
  const float* ffn_b2   = (const float*)d_in[14];
  const float* ln2_g    = (const float*)d_in[15];
  const float* ln2_b    = (const float*)d_in[16];
  const float* rel_w1   = (const float*)d_in[17];
  const float* rel_b1   = (const float*)d_in[18];
  const float* rel_w2   = (const float*)d_in[19];
  const float* rel_b2   = (const float*)d_in[20];
  float* out = (float*)d_out;

  float *px, *pqkv, *pffn, *pA, *pBm;
  cudaGetSymbolAddress((void**)&px,    g_x);
  cudaGetSymbolAddress((void**)&pqkv,  g_qkv);
  cudaGetSymbolAddress((void**)&pffn,  g_ffn);
  cudaGetSymbolAddress((void**)&pA,    g_A);
  cudaGetSymbolAddress((void**)&pBm,   g_Bm);
  float* ppart = pqkv;             // split-K partials (2 * ROWS*DD floats <= ROWS*3*DD)
  float* ppo   = pffn;             // attention partial outputs (SPLITS*BHQ*32 = ROWS*DFF_)
  float* ppl   = pA;               // attention partial l sums (SPLITS*BHQ)

  const int pair_smem = (128 * SP + 128) * sizeof(float);  // ~66KB
  cudaFuncSetAttribute(k_pair, cudaFuncAttributeMaxDynamicSharedMemorySize, pair_smem);

  // encoder: relu(agents @ enc_w + b) -> LN  (K=64, single "split")
  k_gemmP<0><<<dim3(ROWS / 32, 1, 1), 128>>>(agents, nullptr, nullptr, FF, FF,
                                             enc_w, ppart);
  k_combln<1, 0, 0><<<ROWS / 8, 256>>>(ppart, nullptr, enc_b, nullptr,
                                       enc_g, enc_beta, px);

  for (int l = 0; l < LL; l++) {
    // qkv
    k_gemmA<0><<<dim3(ROWS / 64, 3), 128>>>(px, DD, qkv_w + (size_t)l * DD * 3 * DD,
                                            3 * DD, qkv_b + (size_t)l * 3 * DD, pqkv, nullptr);
    // attention partials (branch-free, unnormalized)
    k_attn_part<<<dim3(SPLITS, HH, BB), 256>>>(pqkv, ppo, ppl);
    // proj (attention combine fused into A-load), split-K x2 -> partials
    k_gemmP<1><<<dim3(ROWS / 32, 1, 2), 128>>>(nullptr, ppo, ppl, DD, DD / 2,
                                               attn_ow + (size_t)l * DD * DD, ppart);
    k_combln<0, 1, 1><<<ROWS / 8, 256>>>(ppart, ppart + (size_t)ROWS * DD,
                                         attn_ob + (size_t)l * DD, px,
                                         ln1_g + (size_t)l * DD, ln1_b + (size_t)l * DD, px);
    // ffn1
    k_gemmA<1><<<dim3(ROWS / 64, 4), 128>>>(px, DD, ffn_w1 + (size_t)l * DD * DFF_,
                                            DFF_, ffn_b1 + (size_t)l * DFF_, pffn, nullptr);
    // ffn2 split-K x2 -> partials
    k_gemmP<0><<<dim3(ROWS / 32, 1, 2), 128>>>(pffn, nullptr, nullptr, DFF_, DFF_ / 2,
                                               ffn_w2 + (size_t)l * DFF_ * DD, ppart);
    k_combln<0, 1, 1><<<ROWS / 8, 256>>>(ppart, ppart + (size_t)ROWS * DD,
                                         ffn_b2 + (size_t)l * DD, px,
                                         ln2_g + (size_t)l * DD, ln2_b + (size_t)l * DD, px);
  }

  // pair precompute: A = x@W1[:D]+b1 ; Bm = x@W1[D:]
  k_gemmA<5><<<dim3(ROWS / 64, 1, 2), 128>>>(px, DD, rel_w1, DD, rel_b1, pA, pBm);

  k_pair<<<dim3(NN / 64, NN / 64, BB), 256, pair_smem>>>(rel_w2, rel_b2, out);
}

// round 8
// speedup vs baseline: 1.3338x; 1.0134x over previous
#include <cuda_runtime.h>

#define BB 16
#define NN 256
#define FF 64
#define DD 128
#define HH 4
#define DHH 32
#define DFF_ 512
#define LL 2
#define ROWS (BB*NN)     // 4096
#define PP (NN*(NN-1))   // 65280
#define EPSF 1e-5f
#define SPLITS 4
#define BHQ (BB*HH*NN)   // 16384

// ---------------- scratch ----------------
__device__ float g_x[ROWS*DD];
__device__ float g_qkv[ROWS*3*DD];    // qkv; later reused for GEMM split-K partials
__device__ float g_ffn[ROWS*DFF_];    // ffn1 acts; also attention po scratch (SPLITS*BHQ*32 = 2097152 exact)
__device__ float g_A[ROWS*DD];        // pairpre A; also attention l scratch (SPLITS*BHQ = 65536)
__device__ float g_Bm[ROWS*DD];

typedef unsigned long long u64;

__device__ __forceinline__ u64 pack2(float x, float y) {
  u64 r; asm("mov.b64 %0, {%1, %2};" : "=l"(r) : "f"(x), "f"(y)); return r;
}
__device__ __forceinline__ float2 unpack2(u64 v) {
  float2 r; asm("mov.b64 {%0, %1}, %2;" : "=f"(r.x), "=f"(r.y) : "l"(v)); return r;
}
__device__ __forceinline__ void ffma2(u64 &d, u64 a, u64 b) {
  asm("fma.rn.f32x2 %0, %1, %2, %0;" : "+l"(d) : "l"(a), "l"(b));
}
__device__ __forceinline__ u64 add2(u64 a, u64 b) {
  u64 o; asm("add.rn.f32x2 %0, %1, %2;" : "=l"(o) : "l"(a), "l"(b)); return o;
}
__device__ __forceinline__ u64 relu2(u64 v) {
  float2 f = unpack2(v);
  return pack2(fmaxf(f.x, 0.f), fmaxf(f.y, 0.f));
}

// ================ GEMM A: BM=64, BN=128, BK=16, 128 threads, 8x8 thread tile ================
// EPI: 0 = +bias ; 1 = +bias,relu ; 5 = pairpre dual (blockIdx.z selects W half / output)
template <int EPI>
__global__ void __launch_bounds__(128) k_gemmA(
    const float* __restrict__ X, int KK,
    const float* __restrict__ W, int NOUT,
    const float* __restrict__ bias,
    float* __restrict__ Y, float* __restrict__ Y2) {
  __shared__ float As[2][16][64];
  __shared__ float Bs[2][16][128];
  const int t  = threadIdx.x;
  const int tx = t & 15, ty = t >> 4;
  const int bm0 = blockIdx.x * 64, bn0 = blockIdx.y * 128;
  const int r0 = ty * 8, c0 = tx * 8;
  const int am = t >> 1,  akq = (t & 1) * 8;
  const int bkr = t >> 3, bcq = (t & 7) * 16;

  if (EPI == 5) {
    if (blockIdx.z) { W += (size_t)KK * NOUT; Y = Y2; bias = nullptr; }
  }

  u64 acc[8][4];
  {
    u64 i0 = 0, i1 = 0, i2 = 0, i3 = 0;
    if (EPI != 5 || bias) {
      if (bias) {
        float4 bv0 = *(const float4*)&bias[bn0 + c0];
        float4 bv1 = *(const float4*)&bias[bn0 + c0 + 4];
        i0 = pack2(bv0.x, bv0.y); i1 = pack2(bv0.z, bv0.w);
        i2 = pack2(bv1.x, bv1.y); i3 = pack2(bv1.z, bv1.w);
      }
    }
    #pragma unroll
    for (int i = 0; i < 8; i++) { acc[i][0]=i0; acc[i][1]=i1; acc[i][2]=i2; acc[i][3]=i3; }
  }

  const float* Xp = X + (size_t)(bm0 + am) * KK + akq;
  const float* Wp = W + (size_t)bkr * NOUT + bn0 + bcq;
  const int NT = KK >> 4;

  float4 a0 = *(const float4*)Xp;
  float4 a1 = *(const float4*)(Xp + 4);
  float4 b0 = *(const float4*)Wp;
  float4 b1 = *(const float4*)(Wp + 4);
  float4 b2 = *(const float4*)(Wp + 8);
  float4 b3 = *(const float4*)(Wp + 12);
  {
    As[0][akq + 0][am] = a0.x; As[0][akq + 1][am] = a0.y;
    As[0][akq + 2][am] = a0.z; As[0][akq + 3][am] = a0.w;
    As[0][akq + 4][am] = a1.x; As[0][akq + 5][am] = a1.y;
    As[0][akq + 6][am] = a1.z; As[0][akq + 7][am] = a1.w;
    *(float4*)&Bs[0][bkr][bcq]      = b0;
    *(float4*)&Bs[0][bkr][bcq + 4]  = b1;
    *(float4*)&Bs[0][bkr][bcq + 8]  = b2;
    *(float4*)&Bs[0][bkr][bcq + 12] = b3;
  }
  __syncthreads();

  for (int it = 0; it < NT; it++) {
    const int buf = it & 1;
    if (it + 1 < NT) {
      const float* xp = Xp + (it + 1) * 16;
      a0 = *(const float4*)xp; a1 = *(const float4*)(xp + 4);
      const float* wp = Wp + (size_t)(it + 1) * 16 * NOUT;
      b0 = *(const float4*)wp;        b1 = *(const float4*)(wp + 4);
      b2 = *(const float4*)(wp + 8);  b3 = *(const float4*)(wp + 12);
    }
    #pragma unroll
    for (int k = 0; k < 16; k++) {
      float4 av0 = *(const float4*)&As[buf][k][r0];
      float4 av1 = *(const float4*)&As[buf][k][r0 + 4];
      ulonglong2 bv0 = *(const ulonglong2*)&Bs[buf][k][c0];
      ulonglong2 bv1 = *(const ulonglong2*)&Bs[buf][k][c0 + 4];
      u64 pa[8];
      pa[0] = pack2(av0.x, av0.x); pa[1] = pack2(av0.y, av0.y);
      pa[2] = pack2(av0.z, av0.z); pa[3] = pack2(av0.w, av0.w);
      pa[4] = pack2(av1.x, av1.x); pa[5] = pack2(av1.y, av1.y);
      pa[6] = pack2(av1.z, av1.z); pa[7] = pack2(av1.w, av1.w);
      #pragma unroll
      for (int i = 0; i < 8; i++) {
        ffma2(acc[i][0], pa[i], bv0.x);
        ffma2(acc[i][1], pa[i], bv0.y);
        ffma2(acc[i][2], pa[i], bv1.x);
        ffma2(acc[i][3], pa[i], bv1.y);
      }
    }
    if (it + 1 < NT) {
      const int nb = buf ^ 1;
      As[nb][akq + 0][am] = a0.x; As[nb][akq + 1][am] = a0.y;
      As[nb][akq + 2][am] = a0.z; As[nb][akq + 3][am] = a0.w;
      As[nb][akq + 4][am] = a1.x; As[nb][akq + 5][am] = a1.y;
      As[nb][akq + 6][am] = a1.z; As[nb][akq + 7][am] = a1.w;
      *(float4*)&Bs[nb][bkr][bcq]      = b0;
      *(float4*)&Bs[nb][bkr][bcq + 4]  = b1;
      *(float4*)&Bs[nb][bkr][bcq + 8]  = b2;
      *(float4*)&Bs[nb][bkr][bcq + 12] = b3;
    }
    __syncthreads();
  }

  #pragma unroll
  for (int i = 0; i < 8; i++) {
    float2 u0 = unpack2(acc[i][0]), u1 = unpack2(acc[i][1]);
    float2 u2 = unpack2(acc[i][2]), u3 = unpack2(acc[i][3]);
    float4 f0 = make_float4(u0.x, u0.y, u1.x, u1.y);
    float4 f1 = make_float4(u2.x, u2.y, u3.x, u3.y);
    if (EPI == 1) {
      f0.x = fmaxf(f0.x, 0.f); f0.y = fmaxf(f0.y, 0.f);
      f0.z = fmaxf(f0.z, 0.f); f0.w = fmaxf(f0.w, 0.f);
      f1.x = fmaxf(f1.x, 0.f); f1.y = fmaxf(f1.y, 0.f);
      f1.z = fmaxf(f1.z, 0.f); f1.w = fmaxf(f1.w, 0.f);
    }
    float* yp = &Y[(size_t)(bm0 + r0 + i) * NOUT + bn0 + c0];
    *(float4*)yp       = f0;
    *(float4*)(yp + 4) = f1;
  }
}

// ================ GEMM P: partial split-K, BM=32, BN=128, BK=16, 128 threads, 4x8 tile ================
// blockIdx.z = K-split. ATTN: A elements are attention-combined outputs from (po, l) partials.
template <int ATTN>
__global__ void __launch_bounds__(128) k_gemmP(
    const float* __restrict__ X,
    const float* __restrict__ po, const float* __restrict__ pl,
    int KK, int KH,
    const float* __restrict__ W,
    float* __restrict__ Yp) {
  __shared__ float As[2][16][32];
  __shared__ float Bs[2][16][128];
  const int t  = threadIdx.x;
  const int tx = t & 15, ty = t >> 4;
  const int bm0 = blockIdx.x * 32;
  const int z   = blockIdx.z;
  const int r0 = ty * 4, c0 = tx * 8;
  const int am = t >> 2,  akq = (t & 3) * 4;
  const int bkr = t >> 3, bcq = (t & 7) * 16;

  const int row = bm0 + am;
  const int kb  = z * KH + akq;

  int bq_b = 0, bq_q = 0;
  if (ATTN) { bq_b = row >> 8; bq_q = row & 255; }

  u64 acc[4][4];
  #pragma unroll
  for (int i = 0; i < 4; i++) { acc[i][0]=0; acc[i][1]=0; acc[i][2]=0; acc[i][3]=0; }

  const float* Xp = X + (size_t)row * KK + kb;
  const float* Wp = W + (size_t)(z * KH + bkr) * 128 + bcq;
  const int NT = KH >> 4;

  auto loadA = [&](int it) -> float4 {
    if (!ATTN) {
      return *(const float4*)(Xp + it * 16);
    } else {
      const int kk = kb + it * 16;      // global k in [0,128)
      const int h = kk >> 5, d4 = kk & 31;
      const int bhq = (bq_b * HH + h) * NN + bq_q;
      float lsum = pl[bhq] + pl[BHQ + bhq] + pl[2 * BHQ + bhq] + pl[3 * BHQ + bhq];
      float inv = 1.f / lsum;
      float4 p0 = *(const float4*)&po[((size_t)bhq) * 32 + d4];
      float4 p1 = *(const float4*)&po[((size_t)BHQ + bhq) * 32 + d4];
      float4 p2 = *(const float4*)&po[((size_t)2 * BHQ + bhq) * 32 + d4];
      float4 p3 = *(const float4*)&po[((size_t)3 * BHQ + bhq) * 32 + d4];
      return make_float4((p0.x + p1.x + p2.x + p3.x) * inv,
                         (p0.y + p1.y + p2.y + p3.y) * inv,
                         (p0.z + p1.z + p2.z + p3.z) * inv,
                         (p0.w + p1.w + p2.w + p3.w) * inv);
    }
  };

  float4 a0 = loadA(0);
  float4 b0 = *(const float4*)Wp;
  float4 b1 = *(const float4*)(Wp + 4);
  float4 b2 = *(const float4*)(Wp + 8);
  float4 b3 = *(const float4*)(Wp + 12);
  {
    As[0][akq + 0][am] = a0.x; As[0][akq + 1][am] = a0.y;
    As[0][akq + 2][am] = a0.z; As[0][akq + 3][am] = a0.w;
    *(float4*)&Bs[0][bkr][bcq]      = b0;
    *(float4*)&Bs[0][bkr][bcq + 4]  = b1;
    *(float4*)&Bs[0][bkr][bcq + 8]  = b2;
    *(float4*)&Bs[0][bkr][bcq + 12] = b3;
  }
  __syncthreads();

  for (int it = 0; it < NT; it++) {
    const int buf = it & 1;
    if (it + 1 < NT) {
      a0 = loadA(it + 1);
      const float* wp = Wp + (size_t)(it + 1) * 16 * 128;
      b0 = *(const float4*)wp;        b1 = *(const float4*)(wp + 4);
      b2 = *(const float4*)(wp + 8);  b3 = *(const float4*)(wp + 12);
    }
    #pragma unroll
    for (int k = 0; k < 16; k++) {
      float4 av = *(const float4*)&As[buf][k][r0];
      ulonglong2 bv0 = *(const ulonglong2*)&Bs[buf][k][c0];
      ulonglong2 bv1 = *(const ulonglong2*)&Bs[buf][k][c0 + 4];
      u64 pa0 = pack2(av.x, av.x);
      u64 pa1 = pack2(av.y, av.y);
      u64 pa2 = pack2(av.z, av.z);
      u64 pa3 = pack2(av.w, av.w);
      ffma2(acc[0][0], pa0, bv0.x); ffma2(acc[0][1], pa0, bv0.y);
      ffma2(acc[0][2], pa0, bv1.x); ffma2(acc[0][3], pa0, bv1.y);
      ffma2(acc[1][0], pa1, bv0.x); ffma2(acc[1][1], pa1, bv0.y);
      ffma2(acc[1][2], pa1, bv1.x); ffma2(acc[1][3], pa1, bv1.y);
      ffma2(acc[2][0], pa2, bv0.x); ffma2(acc[2][1], pa2, bv0.y);
      ffma2(acc[2][2], pa2, bv1.x); ffma2(acc[2][3], pa2, bv1.y);
      ffma2(acc[3][0], pa3, bv0.x); ffma2(acc[3][1], pa3, bv0.y);
      ffma2(acc[3][2], pa3, bv1.x); ffma2(acc[3][3], pa3, bv1.y);
    }
    if (it + 1 < NT) {
      const int nb = buf ^ 1;
      As[nb][akq + 0][am] = a0.x; As[nb][akq + 1][am] = a0.y;
      As[nb][akq + 2][am] = a0.z; As[nb][akq + 3][am] = a0.w;
      *(float4*)&Bs[nb][bkr][bcq]      = b0;
      *(float4*)&Bs[nb][bkr][bcq + 4]  = b1;
      *(float4*)&Bs[nb][bkr][bcq + 8]  = b2;
      *(float4*)&Bs[nb][bkr][bcq + 12] = b3;
    }
    __syncthreads();
  }

  float* yp = Yp + (size_t)z * (ROWS * DD) + (size_t)(bm0 + r0) * DD + c0;
  #pragma unroll
  for (int i = 0; i < 4; i++) {
    float2 u0 = unpack2(acc[i][0]), u1 = unpack2(acc[i][1]);
    float2 u2 = unpack2(acc[i][2]), u3 = unpack2(acc[i][3]);
    *(float4*)(yp + (size_t)i * DD)     = make_float4(u0.x, u0.y, u1.x, u1.y);
    *(float4*)(yp + (size_t)i * DD + 4) = make_float4(u2.x, u2.y, u3.x, u3.y);
  }
}

// ================ combine partials + bias (+relu | +res) + LayerNorm; warp per row ================
template <int RELU, int RES, int TWO>
__global__ void __launch_bounds__(256) k_combln(
    const float* __restrict__ p0, const float* __restrict__ p1,
    const float* __restrict__ bias, const float* __restrict__ res,
    const float* __restrict__ g, const float* __restrict__ beta,
    float* __restrict__ Y) {
  const int row = blockIdx.x * 8 + (threadIdx.x >> 5);
  const int lane = threadIdx.x & 31;
  const int c0 = lane * 4;
  const size_t off = (size_t)row * DD + c0;

  float4 v = *(const float4*)&p0[off];
  if (TWO) {
    float4 w = *(const float4*)&p1[off];
    v.x += w.x; v.y += w.y; v.z += w.z; v.w += w.w;
  }
  float4 bv = *(const float4*)&bias[c0];
  v.x += bv.x; v.y += bv.y; v.z += bv.z; v.w += bv.w;
  if (RELU) {
    v.x = fmaxf(v.x, 0.f); v.y = fmaxf(v.y, 0.f);
    v.z = fmaxf(v.z, 0.f); v.w = fmaxf(v.w, 0.f);
  }
  if (RES) {
    float4 r = *(const float4*)&res[off];
    v.x += r.x; v.y += r.y; v.z += r.z; v.w += r.w;
  }
  float s  = v.x + v.y + v.z + v.w;
  float s2 = v.x * v.x + v.y * v.y + v.z * v.z + v.w * v.w;
  #pragma unroll
  for (int o = 16; o; o >>= 1) {
    s  += __shfl_xor_sync(0xffffffffu, s,  o);
    s2 += __shfl_xor_sync(0xffffffffu, s2, o);
  }
  float mu = s * (1.f / 128.f);
  float var = s2 * (1.f / 128.f) - mu * mu;
  float rstd = rsqrtf(var + EPSF);
  float4 gv = *(const float4*)&g[c0];
  float4 ev = *(const float4*)&beta[c0];
  *(float4*)&Y[off] = make_float4(
      (v.x - mu) * rstd * gv.x + ev.x, (v.y - mu) * rstd * gv.y + ev.y,
      (v.z - mu) * rstd * gv.z + ev.z, (v.w - mu) * rstd * gv.w + ev.w);
}

// ================ attention: branch-free split-K partials, 2 queries per thread ================
// SPLITS=4 (64 keys/split). 128 threads; thread t handles queries t and t+128, sharing K/V loads.
// Scores are tiny (|s| < ~5) so softmax without max-subtraction is exact.
__global__ void __launch_bounds__(128) k_attn_part(const float* __restrict__ qkv,
                                                   float* __restrict__ po,
                                                   float* __restrict__ pl) {
  const int split = blockIdx.x, h = blockIdx.y, b = blockIdx.z;
  const int t = threadIdx.x;  // 128
  const int q0 = t, q1 = t + 128;
  __shared__ float Ks[64][DHH], Vs[64][DHH];
  const float* base = qkv + (size_t)b * NN * (3 * DD);
  const int hoff = h * DHH;
  const int kbase = split * 64;

  for (int c = t; c < 64 * DHH / 4; c += 128) {
    int r = c >> 3, d4 = (c & 7) << 2;
    *(float4*)&Ks[r][d4] = *(const float4*)&base[(size_t)(kbase + r) * (3 * DD) + DD     + hoff + d4];
    *(float4*)&Vs[r][d4] = *(const float4*)&base[(size_t)(kbase + r) * (3 * DD) + 2 * DD + hoff + d4];
  }
  u64 qp0[16], qp1[16];
  {
    const ulonglong2* qa = (const ulonglong2*)(base + (size_t)q0 * (3 * DD) + hoff);
    const ulonglong2* qb = (const ulonglong2*)(base + (size_t)q1 * (3 * DD) + hoff);
    #pragma unroll
    for (int i = 0; i < 8; i++) {
      ulonglong2 u = qa[i]; qp0[2*i] = u.x; qp0[2*i+1] = u.y;
      ulonglong2 v = qb[i]; qp1[2*i] = v.x; qp1[2*i+1] = v.y;
    }
  }
  __syncthreads();

  float l0 = 0.f, l1 = 0.f;
  u64 op0[16], op1[16];
  #pragma unroll
  for (int i = 0; i < 16; i++) { op0[i] = 0ull; op1[i] = 0ull; }
  const float scale = 0.17677669529663687f;  // 1/sqrt(32)

  for (int k = 0; k < 64; k++) {
    const ulonglong2* kr = (const ulonglong2*)&Ks[k][0];
    u64 sa0 = 0, sa1 = 0, sa2 = 0, sa3 = 0;
    u64 sb0 = 0, sb1 = 0, sb2 = 0, sb3 = 0;
    #pragma unroll
    for (int i = 0; i < 4; i++) {
      ulonglong2 ka = kr[2*i], kb = kr[2*i+1];
      ffma2(sa0, qp0[4*i],     ka.x);
      ffma2(sa1, qp0[4*i + 1], ka.y);
      ffma2(sa2, qp0[4*i + 2], kb.x);
      ffma2(sa3, qp0[4*i + 3], kb.y);
      ffma2(sb0, qp1[4*i],     ka.x);
      ffma2(sb1, qp1[4*i + 1], ka.y);
      ffma2(sb2, qp1[4*i + 2], kb.x);
      ffma2(sb3, qp1[4*i + 3], kb.y);
    }
    u64 ra = add2(add2(sa0, sa1), add2(sa2, sa3));
    u64 rb = add2(add2(sb0, sb1), add2(sb2, sb3));
    float2 ua = unpack2(ra), ub = unpack2(rb);
    float p0 = __expf((ua.x + ua.y) * scale);
    float p1 = __expf((ub.x + ub.y) * scale);
    l0 += p0;
    l1 += p1;
    u64 pp0 = pack2(p0, p0), pp1 = pack2(p1, p1);
    const ulonglong2* vr = (const ulonglong2*)&Vs[k][0];
    #pragma unroll
    for (int i = 0; i < 8; i++) {
      ulonglong2 vv = vr[i];
      ffma2(op0[2*i],     pp0, vv.x);
      ffma2(op0[2*i + 1], pp0, vv.y);
      ffma2(op1[2*i],     pp1, vv.x);
      ffma2(op1[2*i + 1], pp1, vv.y);
    }
  }

  const int bh = (b * HH + h) * NN;
  {
    const int bhq = bh + q0;
    float* pop = po + ((size_t)split * BHQ + bhq) * 32;
    #pragma unroll
    for (int i = 0; i < 8; i++) {
      float2 a = unpack2(op0[2*i]), c = unpack2(op0[2*i + 1]);
      *(float4*)&pop[4*i] = make_float4(a.x, a.y, c.x, c.y);
    }
    pl[(size_t)split * BHQ + bhq] = l0;
  }
  {
    const int bhq = bh + q1;
    float* pop = po + ((size_t)split * BHQ + bhq) * 32;
    #pragma unroll
    for (int i = 0; i < 8; i++) {
      float2 a = unpack2(op1[2*i]), c = unpack2(op1[2*i + 1]);
      *(float4*)&pop[4*i] = make_float4(a.x, a.y, c.x, c.y);
    }
    pl[(size_t)split * BHQ + bhq] = l1;
  }
}

// ================ pair kernel: 64i x 64j per block, 4x4 pairs per thread ================
#define SP 132  // padded row stride (floats)
__global__ void __launch_bounds__(256) k_pair(const float* __restrict__ w2,
                                              const float* __restrict__ b2,
                                              float* __restrict__ out) {
  extern __shared__ float sm[];
  float* smA = sm;                   // 64*SP
  float* smB = sm + 64 * SP;         // 64*SP
  float* smw = sm + 128 * SP;        // 128
  const int b  = blockIdx.z;
  const int i0 = blockIdx.x * 64;
  const int j0 = blockIdx.y * 64;
  const int t  = threadIdx.x;  // 256
  const int jx = t & 15, iy = t >> 4;

  {
    const float* Ab = g_A  + ((size_t)(b * NN + i0)) * DD;
    const float* Bb = g_Bm + ((size_t)(b * NN + j0)) * DD;
    for (int idx = t; idx < 64 * 32; idx += 256) {
      int r = idx >> 5, dq = (idx & 31) << 2;
      *(float4*)&smA[r * SP + dq] = *(const float4*)&Ab[(size_t)r * DD + dq];
      *(float4*)&smB[r * SP + dq] = *(const float4*)&Bb[(size_t)r * DD + dq];
    }
    if (t < 32) *(float4*)&smw[t * 4] = *(const float4*)&w2[t * 4];
  }
  __syncthreads();

  const int ibl = iy * 4;
  u64 acc[4][4];
  #pragma unroll
  for (int ii = 0; ii < 4; ii++)
    #pragma unroll
    for (int jj = 0; jj < 4; jj++) acc[ii][jj] = 0ull;

  for (int d = 0; d < DD; d += 4) {
    ulonglong2 wv = *(const ulonglong2*)&smw[d];
    ulonglong2 av[4], bv[4];
    #pragma unroll
    for (int ii = 0; ii < 4; ii++) av[ii] = *(const ulonglong2*)&smA[(ibl + ii) * SP + d];
    #pragma unroll
    for (int jj = 0; jj < 4; jj++) bv[jj] = *(const ulonglong2*)&smB[(jx + 16 * jj) * SP + d];
    #pragma unroll
    for (int ii = 0; ii < 4; ii++) {
      #pragma unroll
      for (int jj = 0; jj < 4; jj++) {
        u64 s0 = relu2(add2(av[ii].x, bv[jj].x));
        ffma2(acc[ii][jj], s0, wv.x);
        u64 s1 = relu2(add2(av[ii].y, bv[jj].y));
        ffma2(acc[ii][jj], s1, wv.y);
      }
    }
  }

  const float b2v = b2[0];
  float* outb = out + (size_t)b * PP;
  #pragma unroll
  for (int ii = 0; ii < 4; ii++) {
    const int i = i0 + ibl + ii;
    #pragma unroll
    for (int jj = 0; jj < 4; jj++) {
      const int j = j0 + jx + 16 * jj;
      if (j != i) {
        float2 u = unpack2(acc[ii][jj]);
        outb[i * (NN - 1) + j - (j > i ? 1 : 0)] = u.x + u.y + b2v;
      }
    }
  }
}

// ================ host ================
extern "C" void kernel_launch(void* const* d_in, const int* in_sizes, int n_in,
                              void* d_out, int out_size) {
  const float* agents   = (const float*)d_in[0];
  const float* enc_w    = (const float*)d_in[1];
  const float* enc_b    = (const float*)d_in[2];
  const float* enc_g    = (const float*)d_in[3];
  const float* enc_beta = (const float*)d_in[4];
  const float* qkv_w    = (const float*)d_in[5];
  const float* qkv_b    = (const float*)d_in[6];
  const float* attn_ow  = (const float*)d_in[7];
  const float* attn_ob  = (const float*)d_in[8];
  const float* ln1_g    = (const float*)d_in[9];
  const float* ln1_b    = (const float*)d_in[10];
  const float* ffn_w1   = (const float*)d_in[11];
  const float* ffn_b1   = (const float*)d_in[12];
  const float* ffn_w2   = (const float*)d_in[13];
  const float* ffn_b2   = (const float*)d_in[14];
  const float* ln2_g    = (const float*)d_in[15];
  const float* ln2_b    = (const float*)d_in[16];
  const float* rel_w1   = (const float*)d_in[17];
  const float* rel_b1   = (const float*)d_in[18];
  const float* rel_w2   = (const float*)d_in[19];
  const float* rel_b2   = (const float*)d_in[20];
  float* out = (float*)d_out;

  float *px, *pqkv, *pffn, *pA, *pBm;
  cudaGetSymbolAddress((void**)&px,    g_x);
  cudaGetSymbolAddress((void**)&pqkv,  g_qkv);
  cudaGetSymbolAddress((void**)&pffn,  g_ffn);
  cudaGetSymbolAddress((void**)&pA,    g_A);
  cudaGetSymbolAddress((void**)&pBm,   g_Bm);
  float* ppart = pqkv;             // split-K partials (2 * ROWS*DD floats <= ROWS*3*DD)
  float* ppo   = pffn;             // attention partial outputs (SPLITS*BHQ*32 = ROWS*DFF_)
  float* ppl   = pA;               // attention partial l sums (SPLITS*BHQ)

  const int pair_smem = (128 * SP + 128) * sizeof(float);  // ~66KB
  cudaFuncSetAttribute(k_pair, cudaFuncAttributeMaxDynamicSharedMemorySize, pair_smem);

  // encoder: relu(agents @ enc_w + b) -> LN  (K=64, single "split")
  k_gemmP<0><<<dim3(ROWS / 32, 1, 1), 128>>>(agents, nullptr, nullptr, FF, FF,
                                             enc_w, ppart);
  k_combln<1, 0, 0><<<ROWS / 8, 256>>>(ppart, nullptr, enc_b, nullptr,
                                       enc_g, enc_beta, px);

  for (int l = 0; l < LL; l++) {
    // qkv
    k_gemmA<0><<<dim3(ROWS / 64, 3), 128>>>(px, DD, qkv_w + (size_t)l * DD * 3 * DD,
                                            3 * DD, qkv_b + (size_t)l * 3 * DD, pqkv, nullptr);
    // attention partials (branch-free, unnormalized, 2 queries/thread)
    k_attn_part<<<dim3(SPLITS, HH, BB), 128>>>(pqkv, ppo, ppl);
    // proj (attention combine fused into A-load), split-K x2 -> partials
    k_gemmP<1><<<dim3(ROWS / 32, 1, 2), 128>>>(nullptr, ppo, ppl, DD, DD / 2,
                                               attn_ow + (size_t)l * DD * DD, ppart);
    k_combln<0, 1, 1><<<ROWS / 8, 256>>>(ppart, ppart + (size_t)ROWS * DD,
                                         attn_ob + (size_t)l * DD, px,
                                         ln1_g + (size_t)l * DD, ln1_b + (size_t)l * DD, px);
    // ffn1
    k_gemmA<1><<<dim3(ROWS / 64, 4), 128>>>(px, DD, ffn_w1 + (size_t)l * DD * DFF_,
                                            DFF_, ffn_b1 + (size_t)l * DFF_, pffn, nullptr);
    // ffn2 split-K x2 -> partials
    k_gemmP<0><<<dim3(ROWS / 32, 1, 2), 128>>>(pffn, nullptr, nullptr, DFF_, DFF_ / 2,
                                               ffn_w2 + (size_t)l * DFF_ * DD, ppart);
    k_combln<0, 1, 1><<<ROWS / 8, 256>>>(ppart, ppart + (size_t)ROWS * DD,
                                         ffn_b2 + (size_t)l * DD, px,
                                         ln2_g + (size_t)l * DD, ln2_b + (size_t)l * DD, px);
  }

  // pair precompute: A = x@W1[:D]+b1 ; Bm = x@W1[D:]
  k_gemmA<5><<<dim3(ROWS / 64, 1, 2), 128>>>(px, DD, rel_w1, DD, rel_b1, pA, pBm);

  k_pair<<<dim3(NN / 64, NN / 64, BB), 256, pair_smem>>>(rel_w2, rel_b2, out);
}